// round 1
// baseline (speedup 1.0000x reference)
#include <cuda_runtime.h>
#include <math.h>

// ---------------- scratch (no allocations allowed) ----------------
__device__ float g_Qm[2048*1024];
__device__ float g_Km[2048*1024];
__device__ float g_Vm[2048*1024];
__device__ float g_word[2048*1024];
__device__ float g_Qc[2048*1024];
__device__ float g_Kc[1024*1024];
__device__ float g_Vc[1024*1024];
__device__ float g_cross[2048*1024];
__device__ float g_Hf[2048*4096];

// ---------------- GEMM: C[M,N] = A[M,K] @ W[N,K]^T + bias, optional ReLU ----
// 128x128x16 tiles, 256 threads, 8x8 per-thread microtile, fp32.
template<bool RELU>
__global__ __launch_bounds__(256)
void gemm_tn(const float* __restrict__ A, const float* __restrict__ W,
             const float* __restrict__ bias, float* __restrict__ C,
             int M, int N, int K)
{
    const int BM = 128, BN = 128, BK = 16;
    __shared__ float As[BK][BM + 4];
    __shared__ float Ws[BK][BN + 4];

    int tid = threadIdx.x;
    int bm = blockIdx.y * BM;
    int bn = blockIdx.x * BN;
    int tx = tid & 15, ty = tid >> 4;

    // loader mapping: each thread loads 2 float4 from A and 2 from W per BK-step
    int lrow = tid >> 2;           // 0..63
    int lkq  = (tid & 3) * 4;      // 0,4,8,12

    float acc[8][8];
    #pragma unroll
    for (int i = 0; i < 8; i++)
        #pragma unroll
        for (int j = 0; j < 8; j++) acc[i][j] = 0.f;

    for (int kb = 0; kb < K; kb += BK) {
        float4 a0 = *(const float4*)&A[(size_t)(bm + lrow)      * K + kb + lkq];
        float4 a1 = *(const float4*)&A[(size_t)(bm + lrow + 64) * K + kb + lkq];
        float4 w0 = *(const float4*)&W[(size_t)(bn + lrow)      * K + kb + lkq];
        float4 w1 = *(const float4*)&W[(size_t)(bn + lrow + 64) * K + kb + lkq];
        __syncthreads();
        As[lkq+0][lrow] = a0.x; As[lkq+1][lrow] = a0.y;
        As[lkq+2][lrow] = a0.z; As[lkq+3][lrow] = a0.w;
        As[lkq+0][lrow+64] = a1.x; As[lkq+1][lrow+64] = a1.y;
        As[lkq+2][lrow+64] = a1.z; As[lkq+3][lrow+64] = a1.w;
        Ws[lkq+0][lrow] = w0.x; Ws[lkq+1][lrow] = w0.y;
        Ws[lkq+2][lrow] = w0.z; Ws[lkq+3][lrow] = w0.w;
        Ws[lkq+0][lrow+64] = w1.x; Ws[lkq+1][lrow+64] = w1.y;
        Ws[lkq+2][lrow+64] = w1.z; Ws[lkq+3][lrow+64] = w1.w;
        __syncthreads();

        #pragma unroll
        for (int k = 0; k < BK; k++) {
            float ar[8], br[8];
            *(float4*)&ar[0] = *(const float4*)&As[k][ty*8];
            *(float4*)&ar[4] = *(const float4*)&As[k][ty*8 + 4];
            *(float4*)&br[0] = *(const float4*)&Ws[k][tx*8];
            *(float4*)&br[4] = *(const float4*)&Ws[k][tx*8 + 4];
            #pragma unroll
            for (int i = 0; i < 8; i++)
                #pragma unroll
                for (int j = 0; j < 8; j++)
                    acc[i][j] += ar[i] * br[j];
        }
    }

    #pragma unroll
    for (int i = 0; i < 8; i++) {
        int row = bm + ty*8 + i;
        #pragma unroll
        for (int j = 0; j < 8; j++) {
            float v = acc[i][j] + bias[bn + tx*8 + j];
            if (RELU) v = fmaxf(v, 0.f);
            acc[i][j] = v;
        }
        *(float4*)&C[(size_t)row * N + bn + tx*8]     = *(float4*)&acc[i][0];
        *(float4*)&C[(size_t)row * N + bn + tx*8 + 4] = *(float4*)&acc[i][4];
    }
}

// ---------------- Flash attention, head dim 64, H=16, ld=1024 --------------
// grid: (Sq/64, 16). 256 threads = 8 warps; warp w owns rows w*8..w*8+7.
// Lane owns score/P columns {lane, lane+32} and output dims {lane, lane+32}.
__global__ __launch_bounds__(256)
void attn64(const float* __restrict__ Qp, const float* __restrict__ Kp,
            const float* __restrict__ Vp, float* __restrict__ Op,
            int Sk, int causal)
{
    const int D = 64, LD = 1024, BR = 64, BC = 64, PIT = 65;
    extern __shared__ float sm[];
    float* Qs = sm;                // [64][65]
    float* Ks = Qs + BR * PIT;     // [64][65]
    float* Vs = Ks + BC * PIT;     // [64][65]
    float* Ps = Vs + BC * PIT;     // [64][65]

    int h    = blockIdx.y;
    int r0   = blockIdx.x * BR;
    int tid  = threadIdx.x;
    int warp = tid >> 5, lane = tid & 31;

    for (int i = tid; i < BR * D; i += 256) {
        int r = i >> 6, d = i & 63;
        Qs[r * PIT + d] = Qp[(size_t)(r0 + r) * LD + h * D + d];
    }

    float m[8], l[8], o0[8], o1[8];
    #pragma unroll
    for (int r = 0; r < 8; r++) { m[r] = -1e30f; l[r] = 0.f; o0[r] = 0.f; o1[r] = 0.f; }

    int nt = causal ? (blockIdx.x + 1) : (Sk / BC);
    for (int t = 0; t < nt; t++) {
        int c0 = t * BC;
        __syncthreads();
        for (int i = tid; i < BC * D; i += 256) {
            int r = i >> 6, d = i & 63;
            Ks[r * PIT + d] = Kp[(size_t)(c0 + r) * LD + h * D + d];
            Vs[r * PIT + d] = Vp[(size_t)(c0 + r) * LD + h * D + d];
        }
        __syncthreads();

        // S = Q K^T (lane cols: lane, lane+32)
        float s0[8], s1[8];
        #pragma unroll
        for (int r = 0; r < 8; r++) { s0[r] = 0.f; s1[r] = 0.f; }
        #pragma unroll 8
        for (int d = 0; d < D; d++) {
            float k0 = Ks[lane * PIT + d];
            float k1 = Ks[(lane + 32) * PIT + d];
            #pragma unroll
            for (int r = 0; r < 8; r++) {
                float q = Qs[(warp * 8 + r) * PIT + d];
                s0[r] += q * k0;
                s1[r] += q * k1;
            }
        }

        bool diag = (causal != 0) && (t == nt - 1);
        #pragma unroll
        for (int r = 0; r < 8; r++) {
            int gr = r0 + warp * 8 + r;
            float v0 = s0[r] * 0.125f;
            float v1 = s1[r] * 0.125f;
            if (diag) {
                if (c0 + lane      > gr) v0 = -1e30f;
                if (c0 + lane + 32 > gr) v1 = -1e30f;
            }
            float mx = fmaxf(v0, v1);
            #pragma unroll
            for (int off = 16; off; off >>= 1)
                mx = fmaxf(mx, __shfl_xor_sync(0xffffffffu, mx, off));
            float mn = fmaxf(m[r], mx);
            float p0 = __expf(v0 - mn);
            float p1 = __expf(v1 - mn);
            float corr = __expf(m[r] - mn);
            m[r] = mn;
            float ps = p0 + p1;
            #pragma unroll
            for (int off = 16; off; off >>= 1)
                ps += __shfl_xor_sync(0xffffffffu, ps, off);
            l[r] = l[r] * corr + ps;
            o0[r] *= corr; o1[r] *= corr;
            Ps[(warp * 8 + r) * PIT + lane]      = p0;
            Ps[(warp * 8 + r) * PIT + lane + 32] = p1;
        }
        __syncwarp();

        // O += P V  (lane dims: lane, lane+32)
        #pragma unroll 8
        for (int j = 0; j < BC; j++) {
            float v0 = Vs[j * PIT + lane];
            float v1 = Vs[j * PIT + lane + 32];
            #pragma unroll
            for (int r = 0; r < 8; r++) {
                float p = Ps[(warp * 8 + r) * PIT + j];
                o0[r] += p * v0;
                o1[r] += p * v1;
            }
        }
    }

    #pragma unroll
    for (int r = 0; r < 8; r++) {
        float inv = 1.f / l[r];
        int gr = r0 + warp * 8 + r;
        Op[(size_t)gr * LD + h * D + lane]      = o0[r] * inv;
        Op[(size_t)gr * LD + h * D + lane + 32] = o1[r] * inv;
    }
}

// ---------------- launch ----------------
extern "C" void kernel_launch(void* const* d_in, const int* in_sizes, int n_in,
                              void* d_out, int out_size)
{
    const float* wemb = (const float*)d_in[0];
    const float* pemb = (const float*)d_in[1];
    const float* Wq_m = (const float*)d_in[2];
    const float* bq_m = (const float*)d_in[3];
    const float* Wk_m = (const float*)d_in[4];
    const float* bk_m = (const float*)d_in[5];
    const float* Wv_m = (const float*)d_in[6];
    const float* bv_m = (const float*)d_in[7];
    const float* Wq_c = (const float*)d_in[8];
    const float* bq_c = (const float*)d_in[9];
    const float* Wk_c = (const float*)d_in[10];
    const float* bk_c = (const float*)d_in[11];
    const float* Wv_c = (const float*)d_in[12];
    const float* bv_c = (const float*)d_in[13];
    const float* W1   = (const float*)d_in[14];
    const float* b1   = (const float*)d_in[15];
    const float* W2   = (const float*)d_in[16];
    const float* b2   = (const float*)d_in[17];
    float* out = (float*)d_out;

    float *Qm, *Km, *Vm, *word, *Qc, *Kc, *Vc, *cross, *Hf;
    cudaGetSymbolAddress((void**)&Qm,    g_Qm);
    cudaGetSymbolAddress((void**)&Km,    g_Km);
    cudaGetSymbolAddress((void**)&Vm,    g_Vm);
    cudaGetSymbolAddress((void**)&word,  g_word);
    cudaGetSymbolAddress((void**)&Qc,    g_Qc);
    cudaGetSymbolAddress((void**)&Kc,    g_Kc);
    cudaGetSymbolAddress((void**)&Vc,    g_Vc);
    cudaGetSymbolAddress((void**)&cross, g_cross);
    cudaGetSymbolAddress((void**)&Hf,    g_Hf);

    const int attn_smem = 4 * 64 * 65 * (int)sizeof(float);  // 66560 B
    cudaFuncSetAttribute((const void*)attn64,
                         cudaFuncAttributeMaxDynamicSharedMemorySize, attn_smem);

    dim3 blk(256);

    // Self-attention QKV projections
    gemm_tn<false><<<dim3(8, 16), blk>>>(wemb, Wq_m, bq_m, Qm, 2048, 1024, 1024);
    gemm_tn<false><<<dim3(8, 16), blk>>>(wemb, Wk_m, bk_m, Km, 2048, 1024, 1024);
    gemm_tn<false><<<dim3(8, 16), blk>>>(wemb, Wv_m, bv_m, Vm, 2048, 1024, 1024);

    // Causal self-attention -> word_emb
    attn64<<<dim3(32, 16), blk, attn_smem>>>(Qm, Km, Vm, word, 2048, 1);

    // Cross-attention projections
    gemm_tn<false><<<dim3(8, 16), blk>>>(word, Wq_c, bq_c, Qc, 2048, 1024, 1024);
    gemm_tn<false><<<dim3(8, 8),  blk>>>(pemb, Wk_c, bk_c, Kc, 1024, 1024, 1024);
    gemm_tn<false><<<dim3(8, 8),  blk>>>(pemb, Wv_c, bv_c, Vc, 1024, 1024, 1024);

    // Cross attention -> cross_emb
    attn64<<<dim3(32, 16), blk, attn_smem>>>(Qc, Kc, Vc, cross, 1024, 0);

    // FFN
    gemm_tn<true ><<<dim3(32, 16), blk>>>(cross, W1, b1, Hf, 2048, 4096, 1024);
    gemm_tn<false><<<dim3(8, 16),  blk>>>(Hf, W2, b2, out, 2048, 1024, 4096);
}

// round 5
// speedup vs baseline: 1.6655x; 1.6655x over previous
#include <cuda_runtime.h>
#include <cuda_bf16.h>
#include <math.h>
#include <stdint.h>

// ===================== scratch (static; no allocations) =====================
__device__ float g_Qm[2048*1024];
__device__ float g_Km[2048*1024];
__device__ float g_Vm[2048*1024];
__device__ float g_word[2048*1024];
__device__ float g_Qc[2048*1024];
__device__ float g_Kc[1024*1024];
__device__ float g_Vc[1024*1024];
__device__ float g_cross[2048*1024];

// split-bf16 K-extended operands (A-layout: [hi,lo,hi], B-layout: [hi,hi,lo])
__device__ __nv_bfloat16 g_wemb2 [2048*3072];
__device__ __nv_bfloat16 g_pemb2 [1024*3072];
__device__ __nv_bfloat16 g_word2 [2048*3072];
__device__ __nv_bfloat16 g_cross2[2048*3072];
__device__ __nv_bfloat16 g_Wqm2[1024*3072];
__device__ __nv_bfloat16 g_Wkm2[1024*3072];
__device__ __nv_bfloat16 g_Wvm2[1024*3072];
__device__ __nv_bfloat16 g_Wqc2[1024*3072];
__device__ __nv_bfloat16 g_Wkc2[1024*3072];
__device__ __nv_bfloat16 g_Wvc2[1024*3072];
__device__ __nv_bfloat16 g_W12 [4096*3072];
__device__ __nv_bfloat16 g_W22 [1024*12288];
__device__ __nv_bfloat16 g_Hf2 [2048*12288];

// ===================== PTX helpers (sm_80-compatible only) =====================
__device__ __forceinline__ uint32_t smem_u32_of(const void* p) {
    uint32_t a;
    asm("{ .reg .u64 t; cvta.to.shared.u64 t, %1; cvt.u32.u64 %0, t; }" : "=r"(a) : "l"(p));
    return a;
}
#define CP_ASYNC16(sm, gp) \
    asm volatile("cp.async.cg.shared.global [%0], [%1], 16;" :: "r"(sm), "l"(gp))
#define CP_COMMIT() asm volatile("cp.async.commit_group;" ::: "memory")
#define CP_WAIT(n)  asm volatile("cp.async.wait_group %0;" :: "n"(n) : "memory")

__device__ __forceinline__ void ldm_x4(uint32_t& r0, uint32_t& r1, uint32_t& r2, uint32_t& r3,
                                       uint32_t addr) {
    asm volatile("ldmatrix.sync.aligned.m8n8.x4.shared.b16 {%0,%1,%2,%3}, [%4];"
                 : "=r"(r0), "=r"(r1), "=r"(r2), "=r"(r3) : "r"(addr));
}
__device__ __forceinline__ void mma16816(float* c, const uint32_t* a,
                                         uint32_t b0, uint32_t b1) {
    asm volatile("mma.sync.aligned.m16n8k16.row.col.f32.bf16.bf16.f32 "
                 "{%0,%1,%2,%3}, {%4,%5,%6,%7}, {%8,%9}, {%0,%1,%2,%3};"
                 : "+f"(c[0]), "+f"(c[1]), "+f"(c[2]), "+f"(c[3])
                 : "r"(a[0]), "r"(a[1]), "r"(a[2]), "r"(a[3]), "r"(b0), "r"(b1));
}

// ===================== split conversion kernels =====================
__device__ __forceinline__ void split1(float v, unsigned short& h, unsigned short& l) {
    __nv_bfloat16 hb = __float2bfloat16(v);
    __nv_bfloat16 lb = __float2bfloat16(v - __bfloat162float(hb));
    h = __bfloat16_as_ushort(hb);
    l = __bfloat16_as_ushort(lb);
}
// MODE 0 (A side): dst row = [hi, lo, hi]   MODE 1 (B side): [hi, hi, lo]
template<int MODE>
__global__ __launch_bounds__(256)
void split_k(const float* __restrict__ src, __nv_bfloat16* __restrict__ dst, int M, int K)
{
    int kq = K >> 2;
    int idx = blockIdx.x * 256 + threadIdx.x;
    if (idx >= M * kq) return;
    int m = idx / kq;
    int k4 = (idx - m * kq) << 2;
    float4 v = *(const float4*)(src + (size_t)m * K + k4);
    unsigned short h0,h1,h2,h3,l0,l1,l2,l3;
    split1(v.x, h0, l0); split1(v.y, h1, l1);
    split1(v.z, h2, l2); split1(v.w, h3, l3);
    ushort4 H = make_ushort4(h0, h1, h2, h3);
    ushort4 L = make_ushort4(l0, l1, l2, l3);
    size_t b = (size_t)m * (3 * (size_t)K);
    unsigned short* D = (unsigned short*)dst;
    if (MODE == 0) {
        *(ushort4*)(D + b + k4)       = H;
        *(ushort4*)(D + b + K + k4)   = L;
        *(ushort4*)(D + b + 2*K + k4) = H;
    } else {
        *(ushort4*)(D + b + k4)       = H;
        *(ushort4*)(D + b + K + k4)   = H;
        *(ushort4*)(D + b + 2*K + k4) = L;
    }
}

// ===================== mma.sync bf16 GEMM =====================
// C[M,N] = A[M,K']@B[N,K']^T + bias. 128x128 CTA tile, BK=32, 4-stage cp.async.
// 8 warps in 4x2 (M x N): warp tile 32x64. m16n8k16 fragments.
// OUT_MODE 0: fp32 out.  OUT_MODE 1: relu + split-bf16 triple layout (stride 3N).
#define NSTAGE   4
#define APITCH   80                  // bytes per 32-bf16 row (64B data + 16B pad)
#define STAGE_A  (128 * APITCH)      // 10240
#define STAGE_AB (2 * STAGE_A)       // 20480
#define GEMM_SMEM (NSTAGE * STAGE_AB) // 81920

template<int OUT_MODE>
__global__ __launch_bounds__(256, 1)
void gemm_tc(const __nv_bfloat16* __restrict__ A, const __nv_bfloat16* __restrict__ B,
             const float* __restrict__ bias, float* __restrict__ Cf,
             __nv_bfloat16* __restrict__ Cs, int M, int N, int K)
{
    extern __shared__ char smem[];
    const uint32_t sb = smem_u32_of(smem);
    const int tid = threadIdx.x, warp = tid >> 5, lane = tid & 31;
    const int warpM = (warp >> 1) * 32, warpN = (warp & 1) * 64;
    const int bm = blockIdx.y * 128, bn = blockIdx.x * 128;
    const int KT = K >> 5;

    // loader mapping: 512 16B chunks per operand, 2 A + 2 B chunks per thread
    const int r0 = tid >> 2,        s0 = (tid & 3);
    const int r1 = r0 + 64,         s1 = s0;
    const __nv_bfloat16* Ab = A + (size_t)bm * K;
    const __nv_bfloat16* Bb = B + (size_t)bn * K;

    // canonical ldmatrix.x4 lane mapping: lanes 0-15 -> rows 0-15 @k0,
    // lanes 16-31 -> rows 0-15 @k8.  Matrices: {rows0-7,k0},{rows8-15,k0},
    // {rows0-7,k8},{rows8-15,k8} -> A frag order r0,r1,r2,r3; B tiles {r0,r2},{r1,r3}.
    const int fRow = lane & 15;
    const int fK   = (lane >> 4) * 8;

    float acc[2][8][4];
    #pragma unroll
    for (int i = 0; i < 2; i++)
        #pragma unroll
        for (int j = 0; j < 8; j++)
            #pragma unroll
            for (int q = 0; q < 4; q++) acc[i][j][q] = 0.f;

    // prologue: fill NSTAGE-1 stages
    #pragma unroll
    for (int s = 0; s < NSTAGE - 1; s++) {
        uint32_t sA = sb + s * STAGE_AB, sB = sA + STAGE_A;
        int kb = s << 5;
        CP_ASYNC16(sA + r0 * APITCH + s0 * 16, Ab + (size_t)r0 * K + kb + s0 * 8);
        CP_ASYNC16(sA + r1 * APITCH + s1 * 16, Ab + (size_t)r1 * K + kb + s1 * 8);
        CP_ASYNC16(sB + r0 * APITCH + s0 * 16, Bb + (size_t)r0 * K + kb + s0 * 8);
        CP_ASYNC16(sB + r1 * APITCH + s1 * 16, Bb + (size_t)r1 * K + kb + s1 * 8);
        CP_COMMIT();
    }

    for (int t = 0; t < KT; t++) {
        CP_WAIT(NSTAGE - 2);
        __syncthreads();
        const int st = t & (NSTAGE - 1);
        const uint32_t sA = sb + st * STAGE_AB, sB = sA + STAGE_A;

        uint32_t a[2][2][4];   // [mt][kt][4]
        uint32_t b[2][4][4];   // [kt][npair][r0..r3]
        #pragma unroll
        for (int mt = 0; mt < 2; mt++)
            #pragma unroll
            for (int kt = 0; kt < 2; kt++)
                ldm_x4(a[mt][kt][0], a[mt][kt][1], a[mt][kt][2], a[mt][kt][3],
                       sA + (uint32_t)(warpM + mt * 16 + fRow) * APITCH + (kt * 16 + fK) * 2);
        #pragma unroll
        for (int np = 0; np < 4; np++)
            #pragma unroll
            for (int kt = 0; kt < 2; kt++)
                ldm_x4(b[kt][np][0], b[kt][np][1], b[kt][np][2], b[kt][np][3],
                       sB + (uint32_t)(warpN + np * 16 + fRow) * APITCH + (kt * 16 + fK) * 2);

        #pragma unroll
        for (int mt = 0; mt < 2; mt++)
            #pragma unroll
            for (int np = 0; np < 4; np++)
                #pragma unroll
                for (int kt = 0; kt < 2; kt++) {
                    mma16816(acc[mt][np * 2 + 0], a[mt][kt], b[kt][np][0], b[kt][np][2]);
                    mma16816(acc[mt][np * 2 + 1], a[mt][kt], b[kt][np][1], b[kt][np][3]);
                }

        // prefetch stage t + NSTAGE - 1
        int tn = t + NSTAGE - 1;
        if (tn < KT) {
            int sn = tn & (NSTAGE - 1);
            uint32_t nA = sb + sn * STAGE_AB, nB = nA + STAGE_A;
            int kb = tn << 5;
            CP_ASYNC16(nA + r0 * APITCH + s0 * 16, Ab + (size_t)r0 * K + kb + s0 * 8);
            CP_ASYNC16(nA + r1 * APITCH + s1 * 16, Ab + (size_t)r1 * K + kb + s1 * 8);
            CP_ASYNC16(nB + r0 * APITCH + s0 * 16, Bb + (size_t)r0 * K + kb + s0 * 8);
            CP_ASYNC16(nB + r1 * APITCH + s1 * 16, Bb + (size_t)r1 * K + kb + s1 * 8);
        }
        CP_COMMIT();
    }

    // ---------------- epilogue ----------------
    #pragma unroll
    for (int mt = 0; mt < 2; mt++) {
        int rg = bm + warpM + mt * 16 + (lane >> 2);
        #pragma unroll
        for (int nt = 0; nt < 8; nt++) {
            int gcol = bn + warpN + nt * 8 + (lane & 3) * 2;
            float bx = __ldg(&bias[gcol]), by = __ldg(&bias[gcol + 1]);
            float* ac = acc[mt][nt];
            if (OUT_MODE == 0) {
                float2 v0 = make_float2(ac[0] + bx, ac[1] + by);
                float2 v1 = make_float2(ac[2] + bx, ac[3] + by);
                *(float2*)&Cf[(size_t)rg * N + gcol]       = v0;
                *(float2*)&Cf[(size_t)(rg + 8) * N + gcol] = v1;
            } else {
                float v0 = fmaxf(ac[0] + bx, 0.f), v1 = fmaxf(ac[1] + by, 0.f);
                float v2 = fmaxf(ac[2] + bx, 0.f), v3 = fmaxf(ac[3] + by, 0.f);
                unsigned short h0,h1,h2,h3,l0,l1,l2,l3;
                split1(v0, h0, l0); split1(v1, h1, l1);
                split1(v2, h2, l2); split1(v3, h3, l3);
                unsigned short* D = (unsigned short*)Cs;
                size_t b0r = (size_t)rg * (3 * (size_t)N);
                size_t b1r = (size_t)(rg + 8) * (3 * (size_t)N);
                *(ushort2*)(D + b0r + gcol)       = make_ushort2(h0, h1);
                *(ushort2*)(D + b0r + N + gcol)   = make_ushort2(l0, l1);
                *(ushort2*)(D + b0r + 2*N + gcol) = make_ushort2(h0, h1);
                *(ushort2*)(D + b1r + gcol)       = make_ushort2(h2, h3);
                *(ushort2*)(D + b1r + N + gcol)   = make_ushort2(l2, l3);
                *(ushort2*)(D + b1r + 2*N + gcol) = make_ushort2(h2, h3);
            }
        }
    }
}

// ===================== flash attention (fp32, LDS-optimized) ================
__global__ __launch_bounds__(256)
void attn64(const float* __restrict__ Qp, const float* __restrict__ Kp,
            const float* __restrict__ Vp, float* __restrict__ Op,
            int Sk, int causal)
{
    const int D = 64, LD = 1024, BR = 64, BC = 64;
    const int QP = 68, KP = 65;
    extern __shared__ float sm[];
    float* Qs = sm;                 // [64][68]
    float* Ks = Qs + BR * QP;       // [64 d][65]
    float* Vs = Ks + D * KP;        // [64 j][65]
    float* Ps = Vs + BC * KP;       // [64][68]

    int h = blockIdx.y;
    int r0 = blockIdx.x * BR;
    int tid = threadIdx.x;
    int warp = tid >> 5, lane = tid & 31;

    for (int i = tid; i < BR * D; i += 256) {
        int r = i >> 6, d = i & 63;
        Qs[r * QP + d] = Qp[(size_t)(r0 + r) * LD + h * D + d];
    }

    float m[8], l[8], o0[8], o1[8];
    #pragma unroll
    for (int r = 0; r < 8; r++) { m[r] = -1e30f; l[r] = 0.f; o0[r] = 0.f; o1[r] = 0.f; }

    int nt = causal ? (blockIdx.x + 1) : (Sk / BC);
    for (int t = 0; t < nt; t++) {
        int c0 = t * BC;
        __syncthreads();
        for (int i = tid; i < BC * D; i += 256) {
            int r = i >> 6, d = i & 63;
            float kv = Kp[(size_t)(c0 + r) * LD + h * D + d];
            float vv = Vp[(size_t)(c0 + r) * LD + h * D + d];
            Ks[d * KP + r] = kv;
            Vs[r * KP + d] = vv;
        }
        __syncthreads();

        float s0[8], s1[8];
        #pragma unroll
        for (int r = 0; r < 8; r++) { s0[r] = 0.f; s1[r] = 0.f; }
        #pragma unroll
        for (int d4 = 0; d4 < D; d4 += 4) {
            float4 qv[8];
            #pragma unroll
            for (int r = 0; r < 8; r++)
                qv[r] = *(const float4*)&Qs[(warp * 8 + r) * QP + d4];
            #pragma unroll
            for (int dd = 0; dd < 4; dd++) {
                float k0 = Ks[(d4 + dd) * KP + lane];
                float k1 = Ks[(d4 + dd) * KP + lane + 32];
                #pragma unroll
                for (int r = 0; r < 8; r++) {
                    float q = (dd == 0) ? qv[r].x : (dd == 1) ? qv[r].y
                            : (dd == 2) ? qv[r].z : qv[r].w;
                    s0[r] += q * k0;
                    s1[r] += q * k1;
                }
            }
        }

        bool diag = (causal != 0) && (t == nt - 1);
        #pragma unroll
        for (int r = 0; r < 8; r++) {
            int gr = r0 + warp * 8 + r;
            float v0 = s0[r] * 0.125f;
            float v1 = s1[r] * 0.125f;
            if (diag) {
                if (c0 + lane      > gr) v0 = -1e30f;
                if (c0 + lane + 32 > gr) v1 = -1e30f;
            }
            float mx = fmaxf(v0, v1);
            #pragma unroll
            for (int off = 16; off; off >>= 1)
                mx = fmaxf(mx, __shfl_xor_sync(0xffffffffu, mx, off));
            float mn = fmaxf(m[r], mx);
            float p0 = __expf(v0 - mn);
            float p1 = __expf(v1 - mn);
            float corr = __expf(m[r] - mn);
            m[r] = mn;
            float ps = p0 + p1;
            #pragma unroll
            for (int off = 16; off; off >>= 1)
                ps += __shfl_xor_sync(0xffffffffu, ps, off);
            l[r] = l[r] * corr + ps;
            o0[r] *= corr; o1[r] *= corr;
            Ps[(warp * 8 + r) * QP + lane]      = p0;
            Ps[(warp * 8 + r) * QP + lane + 32] = p1;
        }
        __syncwarp();

        #pragma unroll
        for (int j4 = 0; j4 < BC; j4 += 4) {
            float4 pv[8];
            #pragma unroll
            for (int r = 0; r < 8; r++)
                pv[r] = *(const float4*)&Ps[(warp * 8 + r) * QP + j4];
            #pragma unroll
            for (int jj = 0; jj < 4; jj++) {
                float v0 = Vs[(j4 + jj) * KP + lane];
                float v1 = Vs[(j4 + jj) * KP + lane + 32];
                #pragma unroll
                for (int r = 0; r < 8; r++) {
                    float p = (jj == 0) ? pv[r].x : (jj == 1) ? pv[r].y
                            : (jj == 2) ? pv[r].z : pv[r].w;
                    o0[r] += p * v0;
                    o1[r] += p * v1;
                }
            }
        }
    }

    #pragma unroll
    for (int r = 0; r < 8; r++) {
        float inv = 1.f / l[r];
        int gr = r0 + warp * 8 + r;
        Op[(size_t)gr * LD + h * D + lane]      = o0[r] * inv;
        Op[(size_t)gr * LD + h * D + lane + 32] = o1[r] * inv;
    }
}

// ===================== launch =====================
static inline dim3 split_grid(int M, int K) { return dim3((M * (K / 4) + 255) / 256); }

extern "C" void kernel_launch(void* const* d_in, const int* in_sizes, int n_in,
                              void* d_out, int out_size)
{
    const float* wemb = (const float*)d_in[0];
    const float* pemb = (const float*)d_in[1];
    const float* Wq_m = (const float*)d_in[2];
    const float* bq_m = (const float*)d_in[3];
    const float* Wk_m = (const float*)d_in[4];
    const float* bk_m = (const float*)d_in[5];
    const float* Wv_m = (const float*)d_in[6];
    const float* bv_m = (const float*)d_in[7];
    const float* Wq_c = (const float*)d_in[8];
    const float* bq_c = (const float*)d_in[9];
    const float* Wk_c = (const float*)d_in[10];
    const float* bk_c = (const float*)d_in[11];
    const float* Wv_c = (const float*)d_in[12];
    const float* bv_c = (const float*)d_in[13];
    const float* W1   = (const float*)d_in[14];
    const float* b1   = (const float*)d_in[15];
    const float* W2   = (const float*)d_in[16];
    const float* b2   = (const float*)d_in[17];
    float* out = (float*)d_out;

    float *Qm, *Km, *Vm, *word, *Qc, *Kc, *Vc, *cross;
    __nv_bfloat16 *wemb2, *pemb2, *word2, *cross2;
    __nv_bfloat16 *Wqm2, *Wkm2, *Wvm2, *Wqc2, *Wkc2, *Wvc2, *W12, *W22, *Hf2;
    cudaGetSymbolAddress((void**)&Qm, g_Qm);
    cudaGetSymbolAddress((void**)&Km, g_Km);
    cudaGetSymbolAddress((void**)&Vm, g_Vm);
    cudaGetSymbolAddress((void**)&word, g_word);
    cudaGetSymbolAddress((void**)&Qc, g_Qc);
    cudaGetSymbolAddress((void**)&Kc, g_Kc);
    cudaGetSymbolAddress((void**)&Vc, g_Vc);
    cudaGetSymbolAddress((void**)&cross, g_cross);
    cudaGetSymbolAddress((void**)&wemb2, g_wemb2);
    cudaGetSymbolAddress((void**)&pemb2, g_pemb2);
    cudaGetSymbolAddress((void**)&word2, g_word2);
    cudaGetSymbolAddress((void**)&cross2, g_cross2);
    cudaGetSymbolAddress((void**)&Wqm2, g_Wqm2);
    cudaGetSymbolAddress((void**)&Wkm2, g_Wkm2);
    cudaGetSymbolAddress((void**)&Wvm2, g_Wvm2);
    cudaGetSymbolAddress((void**)&Wqc2, g_Wqc2);
    cudaGetSymbolAddress((void**)&Wkc2, g_Wkc2);
    cudaGetSymbolAddress((void**)&Wvc2, g_Wvc2);
    cudaGetSymbolAddress((void**)&W12, g_W12);
    cudaGetSymbolAddress((void**)&W22, g_W22);
    cudaGetSymbolAddress((void**)&Hf2, g_Hf2);

    const int attn_smem = (64*68 + 64*65 + 64*65 + 64*68) * (int)sizeof(float); // 68096
    cudaFuncSetAttribute((const void*)attn64,
                         cudaFuncAttributeMaxDynamicSharedMemorySize, attn_smem);
    cudaFuncSetAttribute((const void*)gemm_tc<0>,
                         cudaFuncAttributeMaxDynamicSharedMemorySize, GEMM_SMEM);
    cudaFuncSetAttribute((const void*)gemm_tc<1>,
                         cudaFuncAttributeMaxDynamicSharedMemorySize, GEMM_SMEM);

    // ---- split weights + inputs ----
    split_k<0><<<split_grid(2048, 1024), 256>>>(wemb, wemb2, 2048, 1024);
    split_k<0><<<split_grid(1024, 1024), 256>>>(pemb, pemb2, 1024, 1024);
    split_k<1><<<split_grid(1024, 1024), 256>>>(Wq_m, Wqm2, 1024, 1024);
    split_k<1><<<split_grid(1024, 1024), 256>>>(Wk_m, Wkm2, 1024, 1024);
    split_k<1><<<split_grid(1024, 1024), 256>>>(Wv_m, Wvm2, 1024, 1024);
    split_k<1><<<split_grid(1024, 1024), 256>>>(Wq_c, Wqc2, 1024, 1024);
    split_k<1><<<split_grid(1024, 1024), 256>>>(Wk_c, Wkc2, 1024, 1024);
    split_k<1><<<split_grid(1024, 1024), 256>>>(Wv_c, Wvc2, 1024, 1024);
    split_k<1><<<split_grid(4096, 1024), 256>>>(W1, W12, 4096, 1024);
    split_k<1><<<split_grid(1024, 4096), 256>>>(W2, W22, 1024, 4096);

    // ---- self-attn QKV projections ----
    gemm_tc<0><<<dim3(8, 16), 256, GEMM_SMEM>>>(wemb2, Wqm2, bq_m, Qm, nullptr, 2048, 1024, 3072);
    gemm_tc<0><<<dim3(8, 16), 256, GEMM_SMEM>>>(wemb2, Wkm2, bk_m, Km, nullptr, 2048, 1024, 3072);
    gemm_tc<0><<<dim3(8, 16), 256, GEMM_SMEM>>>(wemb2, Wvm2, bv_m, Vm, nullptr, 2048, 1024, 3072);

    // ---- causal self-attention ----
    attn64<<<dim3(32, 16), 256, attn_smem>>>(Qm, Km, Vm, word, 2048, 1);
    split_k<0><<<split_grid(2048, 1024), 256>>>(word, word2, 2048, 1024);

    // ---- cross projections ----
    gemm_tc<0><<<dim3(8, 16), 256, GEMM_SMEM>>>(word2, Wqc2, bq_c, Qc, nullptr, 2048, 1024, 3072);
    gemm_tc<0><<<dim3(8, 8),  256, GEMM_SMEM>>>(pemb2, Wkc2, bk_c, Kc, nullptr, 1024, 1024, 3072);
    gemm_tc<0><<<dim3(8, 8),  256, GEMM_SMEM>>>(pemb2, Wvc2, bv_c, Vc, nullptr, 1024, 1024, 3072);

    // ---- cross attention ----
    attn64<<<dim3(32, 16), 256, attn_smem>>>(Qc, Kc, Vc, cross, 1024, 0);
    split_k<0><<<split_grid(2048, 1024), 256>>>(cross, cross2, 2048, 1024);

    // ---- FFN ----
    gemm_tc<1><<<dim3(32, 16), 256, GEMM_SMEM>>>(cross2, W12, b1, nullptr, Hf2, 2048, 4096, 3072);
    gemm_tc<0><<<dim3(8, 16),  256, GEMM_SMEM>>>(Hf2, W22, b2, out, nullptr, 2048, 1024, 12288);
}

// round 6
// speedup vs baseline: 2.2732x; 1.3649x over previous
#include <cuda_runtime.h>
#include <cuda_bf16.h>
#include <math.h>
#include <stdint.h>

// ===================== scratch (static; no allocations) =====================
__device__ float g_Qm[2048*1024];
__device__ float g_Km[2048*1024];
__device__ float g_Vm[2048*1024];
__device__ float g_Qc[2048*1024];
__device__ float g_Kc[1024*1024];
__device__ float g_Vc[1024*1024];

// split-bf16 K-extended operands (A-layout: [hi,lo,hi], B-layout: [hi,hi,lo])
__device__ __nv_bfloat16 g_wemb2 [2048*3072];
__device__ __nv_bfloat16 g_pemb2 [1024*3072];
__device__ __nv_bfloat16 g_word2 [2048*3072];
__device__ __nv_bfloat16 g_cross2[2048*3072];
__device__ __nv_bfloat16 g_Wqm2[1024*3072];
__device__ __nv_bfloat16 g_Wkm2[1024*3072];
__device__ __nv_bfloat16 g_Wvm2[1024*3072];
__device__ __nv_bfloat16 g_Wqc2[1024*3072];
__device__ __nv_bfloat16 g_Wkc2[1024*3072];
__device__ __nv_bfloat16 g_Wvc2[1024*3072];
__device__ __nv_bfloat16 g_W12 [4096*3072];
__device__ __nv_bfloat16 g_W22 [1024*12288];
__device__ __nv_bfloat16 g_Hf2 [2048*12288];

// ===================== PTX helpers (sm_80-compatible only) =====================
__device__ __forceinline__ uint32_t smem_u32_of(const void* p) {
    uint32_t a;
    asm("{ .reg .u64 t; cvta.to.shared.u64 t, %1; cvt.u32.u64 %0, t; }" : "=r"(a) : "l"(p));
    return a;
}
#define CP_ASYNC16(sm, gp) \
    asm volatile("cp.async.cg.shared.global [%0], [%1], 16;" :: "r"(sm), "l"(gp))
#define CP_COMMIT() asm volatile("cp.async.commit_group;" ::: "memory")
#define CP_WAIT(n)  asm volatile("cp.async.wait_group %0;" :: "n"(n) : "memory")

__device__ __forceinline__ void ldm_x4(uint32_t& r0, uint32_t& r1, uint32_t& r2, uint32_t& r3,
                                       uint32_t addr) {
    asm volatile("ldmatrix.sync.aligned.m8n8.x4.shared.b16 {%0,%1,%2,%3}, [%4];"
                 : "=r"(r0), "=r"(r1), "=r"(r2), "=r"(r3) : "r"(addr));
}
__device__ __forceinline__ void ldm_x4t(uint32_t& r0, uint32_t& r1, uint32_t& r2, uint32_t& r3,
                                        uint32_t addr) {
    asm volatile("ldmatrix.sync.aligned.m8n8.x4.trans.shared.b16 {%0,%1,%2,%3}, [%4];"
                 : "=r"(r0), "=r"(r1), "=r"(r2), "=r"(r3) : "r"(addr));
}
__device__ __forceinline__ void mma16816(float* c, const uint32_t* a,
                                         uint32_t b0, uint32_t b1) {
    asm volatile("mma.sync.aligned.m16n8k16.row.col.f32.bf16.bf16.f32 "
                 "{%0,%1,%2,%3}, {%4,%5,%6,%7}, {%8,%9}, {%0,%1,%2,%3};"
                 : "+f"(c[0]), "+f"(c[1]), "+f"(c[2]), "+f"(c[3])
                 : "r"(a[0]), "r"(a[1]), "r"(a[2]), "r"(a[3]), "r"(b0), "r"(b1));
}

// ===================== split helpers =====================
__device__ __forceinline__ void split1(float v, unsigned short& h, unsigned short& l) {
    __nv_bfloat16 hb = __float2bfloat16(v);
    __nv_bfloat16 lb = __float2bfloat16(v - __bfloat162float(hb));
    h = __bfloat16_as_ushort(hb);
    l = __bfloat16_as_ushort(lb);
}
// pack 2 floats -> bf16x2 hi and residual lo (low 16 bits = first element)
__device__ __forceinline__ void pack_hl(float a, float b, uint32_t& hi, uint32_t& lo) {
    unsigned short ha, la, hb, lb;
    split1(a, ha, la);
    split1(b, hb, lb);
    hi = ((uint32_t)hb << 16) | ha;
    lo = ((uint32_t)lb << 16) | la;
}

// MODE 0 (A side): dst row = [hi, lo, hi]   MODE 1 (B side): [hi, hi, lo]
template<int MODE>
__global__ __launch_bounds__(256)
void split_k(const float* __restrict__ src, __nv_bfloat16* __restrict__ dst, int M, int K)
{
    int kq = K >> 2;
    int idx = blockIdx.x * 256 + threadIdx.x;
    if (idx >= M * kq) return;
    int m = idx / kq;
    int k4 = (idx - m * kq) << 2;
    float4 v = *(const float4*)(src + (size_t)m * K + k4);
    unsigned short h0,h1,h2,h3,l0,l1,l2,l3;
    split1(v.x, h0, l0); split1(v.y, h1, l1);
    split1(v.z, h2, l2); split1(v.w, h3, l3);
    ushort4 H = make_ushort4(h0, h1, h2, h3);
    ushort4 L = make_ushort4(l0, l1, l2, l3);
    size_t b = (size_t)m * (3 * (size_t)K);
    unsigned short* D = (unsigned short*)dst;
    if (MODE == 0) {
        *(ushort4*)(D + b + k4)       = H;
        *(ushort4*)(D + b + K + k4)   = L;
        *(ushort4*)(D + b + 2*K + k4) = H;
    } else {
        *(ushort4*)(D + b + k4)       = H;
        *(ushort4*)(D + b + K + k4)   = H;
        *(ushort4*)(D + b + 2*K + k4) = L;
    }
}

// ===================== mma.sync bf16 GEMM (validated R5) =====================
#define NSTAGE   4
#define APITCH   80
#define STAGE_A  (128 * APITCH)
#define STAGE_AB (2 * STAGE_A)
#define GEMM_SMEM (NSTAGE * STAGE_AB)

template<int OUT_MODE>
__global__ __launch_bounds__(256, 1)
void gemm_tc(const __nv_bfloat16* __restrict__ A, const __nv_bfloat16* __restrict__ B,
             const float* __restrict__ bias, float* __restrict__ Cf,
             __nv_bfloat16* __restrict__ Cs, int M, int N, int K)
{
    extern __shared__ char smem[];
    const uint32_t sb = smem_u32_of(smem);
    const int tid = threadIdx.x, warp = tid >> 5, lane = tid & 31;
    const int warpM = (warp >> 1) * 32, warpN = (warp & 1) * 64;
    const int bm = blockIdx.y * 128, bn = blockIdx.x * 128;
    const int KT = K >> 5;

    const int r0 = tid >> 2,        s0 = (tid & 3);
    const int r1 = r0 + 64,         s1 = s0;
    const __nv_bfloat16* Ab = A + (size_t)bm * K;
    const __nv_bfloat16* Bb = B + (size_t)bn * K;

    const int fRow = lane & 15;
    const int fK   = (lane >> 4) * 8;

    float acc[2][8][4];
    #pragma unroll
    for (int i = 0; i < 2; i++)
        #pragma unroll
        for (int j = 0; j < 8; j++)
            #pragma unroll
            for (int q = 0; q < 4; q++) acc[i][j][q] = 0.f;

    #pragma unroll
    for (int s = 0; s < NSTAGE - 1; s++) {
        uint32_t sA = sb + s * STAGE_AB, sB = sA + STAGE_A;
        int kb = s << 5;
        CP_ASYNC16(sA + r0 * APITCH + s0 * 16, Ab + (size_t)r0 * K + kb + s0 * 8);
        CP_ASYNC16(sA + r1 * APITCH + s1 * 16, Ab + (size_t)r1 * K + kb + s1 * 8);
        CP_ASYNC16(sB + r0 * APITCH + s0 * 16, Bb + (size_t)r0 * K + kb + s0 * 8);
        CP_ASYNC16(sB + r1 * APITCH + s1 * 16, Bb + (size_t)r1 * K + kb + s1 * 8);
        CP_COMMIT();
    }

    for (int t = 0; t < KT; t++) {
        CP_WAIT(NSTAGE - 2);
        __syncthreads();
        const int st = t & (NSTAGE - 1);
        const uint32_t sA = sb + st * STAGE_AB, sB = sA + STAGE_A;

        uint32_t a[2][2][4];
        uint32_t b[2][4][4];
        #pragma unroll
        for (int mt = 0; mt < 2; mt++)
            #pragma unroll
            for (int kt = 0; kt < 2; kt++)
                ldm_x4(a[mt][kt][0], a[mt][kt][1], a[mt][kt][2], a[mt][kt][3],
                       sA + (uint32_t)(warpM + mt * 16 + fRow) * APITCH + (kt * 16 + fK) * 2);
        #pragma unroll
        for (int np = 0; np < 4; np++)
            #pragma unroll
            for (int kt = 0; kt < 2; kt++)
                ldm_x4(b[kt][np][0], b[kt][np][1], b[kt][np][2], b[kt][np][3],
                       sB + (uint32_t)(warpN + np * 16 + fRow) * APITCH + (kt * 16 + fK) * 2);

        #pragma unroll
        for (int mt = 0; mt < 2; mt++)
            #pragma unroll
            for (int np = 0; np < 4; np++)
                #pragma unroll
                for (int kt = 0; kt < 2; kt++) {
                    mma16816(acc[mt][np * 2 + 0], a[mt][kt], b[kt][np][0], b[kt][np][2]);
                    mma16816(acc[mt][np * 2 + 1], a[mt][kt], b[kt][np][1], b[kt][np][3]);
                }

        int tn = t + NSTAGE - 1;
        if (tn < KT) {
            int sn = tn & (NSTAGE - 1);
            uint32_t nA = sb + sn * STAGE_AB, nB = nA + STAGE_A;
            int kb = tn << 5;
            CP_ASYNC16(nA + r0 * APITCH + s0 * 16, Ab + (size_t)r0 * K + kb + s0 * 8);
            CP_ASYNC16(nA + r1 * APITCH + s1 * 16, Ab + (size_t)r1 * K + kb + s1 * 8);
            CP_ASYNC16(nB + r0 * APITCH + s0 * 16, Bb + (size_t)r0 * K + kb + s0 * 8);
            CP_ASYNC16(nB + r1 * APITCH + s1 * 16, Bb + (size_t)r1 * K + kb + s1 * 8);
        }
        CP_COMMIT();
    }

    #pragma unroll
    for (int mt = 0; mt < 2; mt++) {
        int rg = bm + warpM + mt * 16 + (lane >> 2);
        #pragma unroll
        for (int nt = 0; nt < 8; nt++) {
            int gcol = bn + warpN + nt * 8 + (lane & 3) * 2;
            float bx = __ldg(&bias[gcol]), by = __ldg(&bias[gcol + 1]);
            float* ac = acc[mt][nt];
            if (OUT_MODE == 0) {
                float2 v0 = make_float2(ac[0] + bx, ac[1] + by);
                float2 v1 = make_float2(ac[2] + bx, ac[3] + by);
                *(float2*)&Cf[(size_t)rg * N + gcol]       = v0;
                *(float2*)&Cf[(size_t)(rg + 8) * N + gcol] = v1;
            } else {
                float v0 = fmaxf(ac[0] + bx, 0.f), v1 = fmaxf(ac[1] + by, 0.f);
                float v2 = fmaxf(ac[2] + bx, 0.f), v3 = fmaxf(ac[3] + by, 0.f);
                unsigned short h0,h1,h2,h3,l0,l1,l2,l3;
                split1(v0, h0, l0); split1(v1, h1, l1);
                split1(v2, h2, l2); split1(v3, h3, l3);
                unsigned short* D = (unsigned short*)Cs;
                size_t b0r = (size_t)rg * (3 * (size_t)N);
                size_t b1r = (size_t)(rg + 8) * (3 * (size_t)N);
                *(ushort2*)(D + b0r + gcol)       = make_ushort2(h0, h1);
                *(ushort2*)(D + b0r + N + gcol)   = make_ushort2(l0, l1);
                *(ushort2*)(D + b0r + 2*N + gcol) = make_ushort2(h0, h1);
                *(ushort2*)(D + b1r + gcol)       = make_ushort2(h2, h3);
                *(ushort2*)(D + b1r + N + gcol)   = make_ushort2(l2, l3);
                *(ushort2*)(D + b1r + 2*N + gcol) = make_ushort2(h2, h3);
            }
        }
    }
}

// ===================== tensor-core flash attention ==========================
// BR=BC=64, 4 warps (128 thr), head dim 64, fp32 Q/K/V in, split-bf16 out.
// S = Qhi*Khi + Qlo*Khi + Qhi*Klo (Q pre-scaled by 0.125, exact pow2).
// O += Phi*Vhi + Plo*Vhi + Phi*Vlo; P packed in registers (FA2 layout identity).
// Output written directly in triple split layout [hi | lo | hi], row stride 3*1024.
#define ATTN_PIT 72                       // bf16 elems per smem row (64 + 8 pad)
#define ATTN_PLANE (64 * ATTN_PIT)        // elems per plane
#define ATTN_SMEM (4 * ATTN_PLANE * 2)    // bytes = 36864

template<int CAUSAL>
__global__ __launch_bounds__(128)
void attn_tc(const float* __restrict__ Qp, const float* __restrict__ Kp,
             const float* __restrict__ Vp, __nv_bfloat16* __restrict__ O2,
             int Sk)
{
    const int LD = 1024;
    extern __shared__ __nv_bfloat16 smb[];
    __nv_bfloat16* Khi = smb;
    __nv_bfloat16* Klo = Khi + ATTN_PLANE;
    __nv_bfloat16* Vhi = Klo + ATTN_PLANE;
    __nv_bfloat16* Vlo = Vhi + ATTN_PLANE;
    const uint32_t uKhi = smem_u32_of(Khi);
    const uint32_t uKlo = smem_u32_of(Klo);
    const uint32_t uVhi = smem_u32_of(Vhi);
    const uint32_t uVlo = smem_u32_of(Vlo);

    const int h = blockIdx.y;
    const int r0 = blockIdx.x * 64;
    const int tid = threadIdx.x, w = tid >> 5, lane = tid & 31;
    const int fr = lane & 15, fo = (lane >> 4) * 8;
    const int ldrow = tid >> 1, ldcs = (tid & 1) * 32;   // loader: row 0..63, col seg 0/32

    // ---- stage Q (scaled, split) through Khi/Klo; grab register fragments ----
    {
        const float* Qr = Qp + (size_t)(r0 + ldrow) * LD + h * 64 + ldcs;
        #pragma unroll
        for (int i = 0; i < 8; i++) {
            float4 v = *(const float4*)(Qr + i * 4);
            v.x *= 0.125f; v.y *= 0.125f; v.z *= 0.125f; v.w *= 0.125f;
            unsigned short h0,h1,h2,h3,l0,l1,l2,l3;
            split1(v.x, h0, l0); split1(v.y, h1, l1);
            split1(v.z, h2, l2); split1(v.w, h3, l3);
            *(ushort4*)&Khi[ldrow * ATTN_PIT + ldcs + i * 4] = make_ushort4(h0, h1, h2, h3);
            *(ushort4*)&Klo[ldrow * ATTN_PIT + ldcs + i * 4] = make_ushort4(l0, l1, l2, l3);
        }
    }
    __syncthreads();
    uint32_t qh[4][4], ql[4][4];
    #pragma unroll
    for (int kt = 0; kt < 4; kt++) {
        uint32_t off = (uint32_t)(w * 16 + fr) * (ATTN_PIT * 2) + (kt * 16 + fo) * 2;
        ldm_x4(qh[kt][0], qh[kt][1], qh[kt][2], qh[kt][3], uKhi + off);
        ldm_x4(ql[kt][0], ql[kt][1], ql[kt][2], ql[kt][3], uKlo + off);
    }

    float o[8][4];
    #pragma unroll
    for (int n = 0; n < 8; n++)
        #pragma unroll
        for (int q = 0; q < 4; q++) o[n][q] = 0.f;
    float m0 = -1e30f, m1 = -1e30f, l0 = 0.f, l1 = 0.f;

    const int nt = CAUSAL ? (blockIdx.x + 1) : (Sk >> 6);
    for (int t = 0; t < nt; t++) {
        const int c0 = t * 64;
        // load K,V fp32 tile
        float4 kb[8], vb[8];
        {
            const float* Kr = Kp + (size_t)(c0 + ldrow) * LD + h * 64 + ldcs;
            const float* Vr = Vp + (size_t)(c0 + ldrow) * LD + h * 64 + ldcs;
            #pragma unroll
            for (int i = 0; i < 8; i++) kb[i] = *(const float4*)(Kr + i * 4);
            #pragma unroll
            for (int i = 0; i < 8; i++) vb[i] = *(const float4*)(Vr + i * 4);
        }
        __syncthreads();   // previous tile fully consumed (and Q frags latched)
        #pragma unroll
        for (int i = 0; i < 8; i++) {
            unsigned short h0,h1,h2,h3,l0s,l1s,l2s,l3s;
            split1(kb[i].x, h0, l0s); split1(kb[i].y, h1, l1s);
            split1(kb[i].z, h2, l2s); split1(kb[i].w, h3, l3s);
            *(ushort4*)&Khi[ldrow * ATTN_PIT + ldcs + i * 4] = make_ushort4(h0, h1, h2, h3);
            *(ushort4*)&Klo[ldrow * ATTN_PIT + ldcs + i * 4] = make_ushort4(l0s, l1s, l2s, l3s);
            split1(vb[i].x, h0, l0s); split1(vb[i].y, h1, l1s);
            split1(vb[i].z, h2, l2s); split1(vb[i].w, h3, l3s);
            *(ushort4*)&Vhi[ldrow * ATTN_PIT + ldcs + i * 4] = make_ushort4(h0, h1, h2, h3);
            *(ushort4*)&Vlo[ldrow * ATTN_PIT + ldcs + i * 4] = make_ushort4(l0s, l1s, l2s, l3s);
        }
        __syncthreads();

        // ---- S = Q K^T (split 3-pass) ----
        float s[8][4];
        #pragma unroll
        for (int n = 0; n < 8; n++)
            #pragma unroll
            for (int q = 0; q < 4; q++) s[n][q] = 0.f;
        #pragma unroll
        for (int np = 0; np < 4; np++) {
            uint32_t bh[4][4], bl[4][4];
            #pragma unroll
            for (int kt = 0; kt < 4; kt++) {
                uint32_t off = (uint32_t)(np * 16 + fr) * (ATTN_PIT * 2) + (kt * 16 + fo) * 2;
                ldm_x4(bh[kt][0], bh[kt][1], bh[kt][2], bh[kt][3], uKhi + off);
                ldm_x4(bl[kt][0], bl[kt][1], bl[kt][2], bl[kt][3], uKlo + off);
            }
            #pragma unroll
            for (int kt = 0; kt < 4; kt++) {
                mma16816(s[np*2+0], qh[kt], bh[kt][0], bh[kt][2]);
                mma16816(s[np*2+1], qh[kt], bh[kt][1], bh[kt][3]);
                mma16816(s[np*2+0], ql[kt], bh[kt][0], bh[kt][2]);
                mma16816(s[np*2+1], ql[kt], bh[kt][1], bh[kt][3]);
                mma16816(s[np*2+0], qh[kt], bl[kt][0], bl[kt][2]);
                mma16816(s[np*2+1], qh[kt], bl[kt][1], bl[kt][3]);
            }
        }

        // ---- causal mask on diagonal tile ----
        if (CAUSAL && t == nt - 1) {
            int gr0 = r0 + w * 16 + (lane >> 2);
            int gr1 = gr0 + 8;
            #pragma unroll
            for (int n = 0; n < 8; n++) {
                int col = c0 + n * 8 + (lane & 3) * 2;
                if (col     > gr0) s[n][0] = -1e30f;
                if (col + 1 > gr0) s[n][1] = -1e30f;
                if (col     > gr1) s[n][2] = -1e30f;
                if (col + 1 > gr1) s[n][3] = -1e30f;
            }
        }

        // ---- online softmax (row = quad-group; reduce over lane&3 via xor 1,2) ----
        float mx0 = -1e30f, mx1 = -1e30f;
        #pragma unroll
        for (int n = 0; n < 8; n++) {
            mx0 = fmaxf(mx0, fmaxf(s[n][0], s[n][1]));
            mx1 = fmaxf(mx1, fmaxf(s[n][2], s[n][3]));
        }
        mx0 = fmaxf(mx0, __shfl_xor_sync(0xffffffffu, mx0, 1));
        mx0 = fmaxf(mx0, __shfl_xor_sync(0xffffffffu, mx0, 2));
        mx1 = fmaxf(mx1, __shfl_xor_sync(0xffffffffu, mx1, 1));
        mx1 = fmaxf(mx1, __shfl_xor_sync(0xffffffffu, mx1, 2));
        float mn0 = fmaxf(m0, mx0), mn1 = fmaxf(m1, mx1);
        float cor0 = __expf(m0 - mn0), cor1 = __expf(m1 - mn1);
        m0 = mn0; m1 = mn1;
        float ps0 = 0.f, ps1 = 0.f;
        #pragma unroll
        for (int n = 0; n < 8; n++) {
            s[n][0] = __expf(s[n][0] - mn0);
            s[n][1] = __expf(s[n][1] - mn0);
            s[n][2] = __expf(s[n][2] - mn1);
            s[n][3] = __expf(s[n][3] - mn1);
            ps0 += s[n][0] + s[n][1];
            ps1 += s[n][2] + s[n][3];
        }
        ps0 += __shfl_xor_sync(0xffffffffu, ps0, 1);
        ps0 += __shfl_xor_sync(0xffffffffu, ps0, 2);
        ps1 += __shfl_xor_sync(0xffffffffu, ps1, 1);
        ps1 += __shfl_xor_sync(0xffffffffu, ps1, 2);
        l0 = l0 * cor0 + ps0;
        l1 = l1 * cor1 + ps1;
        #pragma unroll
        for (int n = 0; n < 8; n++) {
            o[n][0] *= cor0; o[n][1] *= cor0;
            o[n][2] *= cor1; o[n][3] *= cor1;
        }

        // ---- pack P (hi + residual lo) into A fragments: k-tile kt <- ntiles 2kt,2kt+1
        uint32_t ph[4][4], pl[4][4];
        #pragma unroll
        for (int kt = 0; kt < 4; kt++) {
            int n0 = 2 * kt, n1 = n0 + 1;
            pack_hl(s[n0][0], s[n0][1], ph[kt][0], pl[kt][0]);
            pack_hl(s[n0][2], s[n0][3], ph[kt][1], pl[kt][1]);
            pack_hl(s[n1][0], s[n1][1], ph[kt][2], pl[kt][2]);
            pack_hl(s[n1][2], s[n1][3], ph[kt][3], pl[kt][3]);
        }

        // ---- O += P V (split 3-pass); V via ldmatrix.trans: ntile pairs {r0,r1},{r2,r3}
        #pragma unroll
        for (int dp = 0; dp < 4; dp++) {
            uint32_t vh[4][4], vl[4][4];
            #pragma unroll
            for (int kj = 0; kj < 4; kj++) {
                uint32_t off = (uint32_t)(kj * 16 + fr) * (ATTN_PIT * 2) + (dp * 16 + fo) * 2;
                ldm_x4t(vh[kj][0], vh[kj][1], vh[kj][2], vh[kj][3], uVhi + off);
                ldm_x4t(vl[kj][0], vl[kj][1], vl[kj][2], vl[kj][3], uVlo + off);
            }
            #pragma unroll
            for (int kj = 0; kj < 4; kj++) {
                mma16816(o[dp*2+0], ph[kj], vh[kj][0], vh[kj][1]);
                mma16816(o[dp*2+1], ph[kj], vh[kj][2], vh[kj][3]);
                mma16816(o[dp*2+0], pl[kj], vh[kj][0], vh[kj][1]);
                mma16816(o[dp*2+1], pl[kj], vh[kj][2], vh[kj][3]);
                mma16816(o[dp*2+0], ph[kj], vl[kj][0], vl[kj][1]);
                mma16816(o[dp*2+1], ph[kj], vl[kj][2], vl[kj][3]);
            }
        }
    }

    // ---- epilogue: O/l -> split triple layout [hi | lo | hi], row stride 3072 ----
    float inv0 = 1.f / l0, inv1 = 1.f / l1;
    int gr0 = r0 + w * 16 + (lane >> 2);
    unsigned short* D = (unsigned short*)O2;
    #pragma unroll
    for (int n = 0; n < 8; n++) {
        int col = h * 64 + n * 8 + (lane & 3) * 2;
        float v0 = o[n][0] * inv0, v1 = o[n][1] * inv0;
        float v2 = o[n][2] * inv1, v3 = o[n][3] * inv1;
        unsigned short h0,h1,h2,h3,l0s,l1s,l2s,l3s;
        split1(v0, h0, l0s); split1(v1, h1, l1s);
        split1(v2, h2, l2s); split1(v3, h3, l3s);
        size_t b0r = (size_t)gr0 * 3072;
        size_t b1r = (size_t)(gr0 + 8) * 3072;
        *(ushort2*)(D + b0r + col)        = make_ushort2(h0, h1);
        *(ushort2*)(D + b0r + 1024 + col) = make_ushort2(l0s, l1s);
        *(ushort2*)(D + b0r + 2048 + col) = make_ushort2(h0, h1);
        *(ushort2*)(D + b1r + col)        = make_ushort2(h2, h3);
        *(ushort2*)(D + b1r + 1024 + col) = make_ushort2(l2s, l3s);
        *(ushort2*)(D + b1r + 2048 + col) = make_ushort2(h2, h3);
    }
}

// ===================== launch =====================
static inline dim3 split_grid(int M, int K) { return dim3((M * (K / 4) + 255) / 256); }

extern "C" void kernel_launch(void* const* d_in, const int* in_sizes, int n_in,
                              void* d_out, int out_size)
{
    const float* wemb = (const float*)d_in[0];
    const float* pemb = (const float*)d_in[1];
    const float* Wq_m = (const float*)d_in[2];
    const float* bq_m = (const float*)d_in[3];
    const float* Wk_m = (const float*)d_in[4];
    const float* bk_m = (const float*)d_in[5];
    const float* Wv_m = (const float*)d_in[6];
    const float* bv_m = (const float*)d_in[7];
    const float* Wq_c = (const float*)d_in[8];
    const float* bq_c = (const float*)d_in[9];
    const float* Wk_c = (const float*)d_in[10];
    const float* bk_c = (const float*)d_in[11];
    const float* Wv_c = (const float*)d_in[12];
    const float* bv_c = (const float*)d_in[13];
    const float* W1   = (const float*)d_in[14];
    const float* b1   = (const float*)d_in[15];
    const float* W2   = (const float*)d_in[16];
    const float* b2   = (const float*)d_in[17];
    float* out = (float*)d_out;

    float *Qm, *Km, *Vm, *Qc, *Kc, *Vc;
    __nv_bfloat16 *wemb2, *pemb2, *word2, *cross2;
    __nv_bfloat16 *Wqm2, *Wkm2, *Wvm2, *Wqc2, *Wkc2, *Wvc2, *W12, *W22, *Hf2;
    cudaGetSymbolAddress((void**)&Qm, g_Qm);
    cudaGetSymbolAddress((void**)&Km, g_Km);
    cudaGetSymbolAddress((void**)&Vm, g_Vm);
    cudaGetSymbolAddress((void**)&Qc, g_Qc);
    cudaGetSymbolAddress((void**)&Kc, g_Kc);
    cudaGetSymbolAddress((void**)&Vc, g_Vc);
    cudaGetSymbolAddress((void**)&wemb2, g_wemb2);
    cudaGetSymbolAddress((void**)&pemb2, g_pemb2);
    cudaGetSymbolAddress((void**)&word2, g_word2);
    cudaGetSymbolAddress((void**)&cross2, g_cross2);
    cudaGetSymbolAddress((void**)&Wqm2, g_Wqm2);
    cudaGetSymbolAddress((void**)&Wkm2, g_Wkm2);
    cudaGetSymbolAddress((void**)&Wvm2, g_Wvm2);
    cudaGetSymbolAddress((void**)&Wqc2, g_Wqc2);
    cudaGetSymbolAddress((void**)&Wkc2, g_Wkc2);
    cudaGetSymbolAddress((void**)&Wvc2, g_Wvc2);
    cudaGetSymbolAddress((void**)&W12, g_W12);
    cudaGetSymbolAddress((void**)&W22, g_W22);
    cudaGetSymbolAddress((void**)&Hf2, g_Hf2);

    cudaFuncSetAttribute((const void*)gemm_tc<0>,
                         cudaFuncAttributeMaxDynamicSharedMemorySize, GEMM_SMEM);
    cudaFuncSetAttribute((const void*)gemm_tc<1>,
                         cudaFuncAttributeMaxDynamicSharedMemorySize, GEMM_SMEM);
    cudaFuncSetAttribute((const void*)attn_tc<0>,
                         cudaFuncAttributeMaxDynamicSharedMemorySize, ATTN_SMEM);
    cudaFuncSetAttribute((const void*)attn_tc<1>,
                         cudaFuncAttributeMaxDynamicSharedMemorySize, ATTN_SMEM);

    // ---- split weights + inputs ----
    split_k<0><<<split_grid(2048, 1024), 256>>>(wemb, wemb2, 2048, 1024);
    split_k<0><<<split_grid(1024, 1024), 256>>>(pemb, pemb2, 1024, 1024);
    split_k<1><<<split_grid(1024, 1024), 256>>>(Wq_m, Wqm2, 1024, 1024);
    split_k<1><<<split_grid(1024, 1024), 256>>>(Wk_m, Wkm2, 1024, 1024);
    split_k<1><<<split_grid(1024, 1024), 256>>>(Wv_m, Wvm2, 1024, 1024);
    split_k<1><<<split_grid(1024, 1024), 256>>>(Wq_c, Wqc2, 1024, 1024);
    split_k<1><<<split_grid(1024, 1024), 256>>>(Wk_c, Wkc2, 1024, 1024);
    split_k<1><<<split_grid(1024, 1024), 256>>>(Wv_c, Wvc2, 1024, 1024);
    split_k<1><<<split_grid(4096, 1024), 256>>>(W1, W12, 4096, 1024);
    split_k<1><<<split_grid(1024, 4096), 256>>>(W2, W22, 1024, 4096);

    // ---- self-attn QKV projections ----
    gemm_tc<0><<<dim3(8, 16), 256, GEMM_SMEM>>>(wemb2, Wqm2, bq_m, Qm, nullptr, 2048, 1024, 3072);
    gemm_tc<0><<<dim3(8, 16), 256, GEMM_SMEM>>>(wemb2, Wkm2, bk_m, Km, nullptr, 2048, 1024, 3072);
    gemm_tc<0><<<dim3(8, 16), 256, GEMM_SMEM>>>(wemb2, Wvm2, bv_m, Vm, nullptr, 2048, 1024, 3072);

    // ---- causal self-attention (writes word2 split directly) ----
    attn_tc<1><<<dim3(32, 16), 128, ATTN_SMEM>>>(Qm, Km, Vm, word2, 2048);

    // ---- cross projections ----
    gemm_tc<0><<<dim3(8, 16), 256, GEMM_SMEM>>>(word2, Wqc2, bq_c, Qc, nullptr, 2048, 1024, 3072);
    gemm_tc<0><<<dim3(8, 8),  256, GEMM_SMEM>>>(pemb2, Wkc2, bk_c, Kc, nullptr, 1024, 1024, 3072);
    gemm_tc<0><<<dim3(8, 8),  256, GEMM_SMEM>>>(pemb2, Wvc2, bv_c, Vc, nullptr, 1024, 1024, 3072);

    // ---- cross attention (writes cross2 split directly) ----
    attn_tc<0><<<dim3(32, 16), 128, ATTN_SMEM>>>(Qc, Kc, Vc, cross2, 1024);

    // ---- FFN ----
    gemm_tc<1><<<dim3(32, 16), 256, GEMM_SMEM>>>(cross2, W12, b1, nullptr, Hf2, 2048, 4096, 3072);
    gemm_tc<0><<<dim3(8, 16),  256, GEMM_SMEM>>>(Hf2, W22, b2, out, nullptr, 2048, 1024, 12288);
}

// round 7
// speedup vs baseline: 2.4467x; 1.0763x over previous
#include <cuda_runtime.h>
#include <cuda_bf16.h>
#include <math.h>
#include <stdint.h>

// ===================== scratch (static; no allocations) =====================
// 2-plane split bf16 QKV: row = [hi(1024) | lo(1024)], stride 2048
__device__ __nv_bfloat16 g_Q2m[2048*2048];
__device__ __nv_bfloat16 g_K2m[2048*2048];
__device__ __nv_bfloat16 g_V2m[2048*2048];
__device__ __nv_bfloat16 g_Q2c[2048*2048];
__device__ __nv_bfloat16 g_K2c[1024*2048];
__device__ __nv_bfloat16 g_V2c[1024*2048];

// triple split-bf16 K-extended operands (A:[hi,lo,hi], B:[hi,hi,lo])
__device__ __nv_bfloat16 g_wemb2 [2048*3072];
__device__ __nv_bfloat16 g_pemb2 [1024*3072];
__device__ __nv_bfloat16 g_word2 [2048*3072];
__device__ __nv_bfloat16 g_cross2[2048*3072];
__device__ __nv_bfloat16 g_Wqm2[1024*3072];
__device__ __nv_bfloat16 g_Wkm2[1024*3072];
__device__ __nv_bfloat16 g_Wvm2[1024*3072];
__device__ __nv_bfloat16 g_Wqc2[1024*3072];
__device__ __nv_bfloat16 g_Wkc2[1024*3072];
__device__ __nv_bfloat16 g_Wvc2[1024*3072];
__device__ __nv_bfloat16 g_W12 [4096*3072];
__device__ __nv_bfloat16 g_W22 [1024*12288];
__device__ __nv_bfloat16 g_Hf2 [2048*12288];

// ===================== PTX helpers (sm_80-compatible only) =====================
__device__ __forceinline__ uint32_t smem_u32_of(const void* p) {
    uint32_t a;
    asm("{ .reg .u64 t; cvta.to.shared.u64 t, %1; cvt.u32.u64 %0, t; }" : "=r"(a) : "l"(p));
    return a;
}
#define CP_ASYNC16(sm, gp) \
    asm volatile("cp.async.cg.shared.global [%0], [%1], 16;" :: "r"(sm), "l"(gp))
#define CP_COMMIT() asm volatile("cp.async.commit_group;" ::: "memory")
#define CP_WAIT(n)  asm volatile("cp.async.wait_group %0;" :: "n"(n) : "memory")

__device__ __forceinline__ void ldm_x4(uint32_t& r0, uint32_t& r1, uint32_t& r2, uint32_t& r3,
                                       uint32_t addr) {
    asm volatile("ldmatrix.sync.aligned.m8n8.x4.shared.b16 {%0,%1,%2,%3}, [%4];"
                 : "=r"(r0), "=r"(r1), "=r"(r2), "=r"(r3) : "r"(addr));
}
__device__ __forceinline__ void ldm_x4t(uint32_t& r0, uint32_t& r1, uint32_t& r2, uint32_t& r3,
                                        uint32_t addr) {
    asm volatile("ldmatrix.sync.aligned.m8n8.x4.trans.shared.b16 {%0,%1,%2,%3}, [%4];"
                 : "=r"(r0), "=r"(r1), "=r"(r2), "=r"(r3) : "r"(addr));
}
__device__ __forceinline__ void mma16816(float* c, const uint32_t* a,
                                         uint32_t b0, uint32_t b1) {
    asm volatile("mma.sync.aligned.m16n8k16.row.col.f32.bf16.bf16.f32 "
                 "{%0,%1,%2,%3}, {%4,%5,%6,%7}, {%8,%9}, {%0,%1,%2,%3};"
                 : "+f"(c[0]), "+f"(c[1]), "+f"(c[2]), "+f"(c[3])
                 : "r"(a[0]), "r"(a[1]), "r"(a[2]), "r"(a[3]), "r"(b0), "r"(b1));
}

// ===================== split helpers =====================
__device__ __forceinline__ void split1(float v, unsigned short& h, unsigned short& l) {
    __nv_bfloat16 hb = __float2bfloat16(v);
    __nv_bfloat16 lb = __float2bfloat16(v - __bfloat162float(hb));
    h = __bfloat16_as_ushort(hb);
    l = __bfloat16_as_ushort(lb);
}
__device__ __forceinline__ void pack_hl(float a, float b, uint32_t& hi, uint32_t& lo) {
    unsigned short ha, la, hb, lb;
    split1(a, ha, la);
    split1(b, hb, lb);
    hi = ((uint32_t)hb << 16) | ha;
    lo = ((uint32_t)lb << 16) | la;
}

// MODE 0 (A side): dst row = [hi, lo, hi]   MODE 1 (B side): [hi, hi, lo]
template<int MODE>
__global__ __launch_bounds__(256)
void split_k(const float* __restrict__ src, __nv_bfloat16* __restrict__ dst, int M, int K)
{
    int kq = K >> 2;
    int idx = blockIdx.x * 256 + threadIdx.x;
    if (idx >= M * kq) return;
    int m = idx / kq;
    int k4 = (idx - m * kq) << 2;
    float4 v = *(const float4*)(src + (size_t)m * K + k4);
    unsigned short h0,h1,h2,h3,l0,l1,l2,l3;
    split1(v.x, h0, l0); split1(v.y, h1, l1);
    split1(v.z, h2, l2); split1(v.w, h3, l3);
    ushort4 H = make_ushort4(h0, h1, h2, h3);
    ushort4 L = make_ushort4(l0, l1, l2, l3);
    size_t b = (size_t)m * (3 * (size_t)K);
    unsigned short* D = (unsigned short*)dst;
    if (MODE == 0) {
        *(ushort4*)(D + b + k4)       = H;
        *(ushort4*)(D + b + K + k4)   = L;
        *(ushort4*)(D + b + 2*K + k4) = H;
    } else {
        *(ushort4*)(D + b + k4)       = H;
        *(ushort4*)(D + b + K + k4)   = H;
        *(ushort4*)(D + b + 2*K + k4) = L;
    }
}

// ===================== mma.sync bf16 GEMM (validated R5) =====================
// OUT_MODE 0: fp32 out. 1: relu + triple split (stride 3N). 2: 2-plane split (stride 2N).
#define NSTAGE   4
#define APITCH   80
#define STAGE_A  (128 * APITCH)
#define STAGE_AB (2 * STAGE_A)
#define GEMM_SMEM (NSTAGE * STAGE_AB)

template<int OUT_MODE>
__global__ __launch_bounds__(256, 1)
void gemm_tc(const __nv_bfloat16* __restrict__ A, const __nv_bfloat16* __restrict__ B,
             const float* __restrict__ bias, float* __restrict__ Cf,
             __nv_bfloat16* __restrict__ Cs, int M, int N, int K)
{
    extern __shared__ char smem[];
    const uint32_t sb = smem_u32_of(smem);
    const int tid = threadIdx.x, warp = tid >> 5, lane = tid & 31;
    const int warpM = (warp >> 1) * 32, warpN = (warp & 1) * 64;
    const int bm = blockIdx.y * 128, bn = blockIdx.x * 128;
    const int KT = K >> 5;

    const int r0 = tid >> 2,        s0 = (tid & 3);
    const int r1 = r0 + 64,         s1 = s0;
    const __nv_bfloat16* Ab = A + (size_t)bm * K;
    const __nv_bfloat16* Bb = B + (size_t)bn * K;

    const int fRow = lane & 15;
    const int fK   = (lane >> 4) * 8;

    float acc[2][8][4];
    #pragma unroll
    for (int i = 0; i < 2; i++)
        #pragma unroll
        for (int j = 0; j < 8; j++)
            #pragma unroll
            for (int q = 0; q < 4; q++) acc[i][j][q] = 0.f;

    #pragma unroll
    for (int s = 0; s < NSTAGE - 1; s++) {
        uint32_t sA = sb + s * STAGE_AB, sB = sA + STAGE_A;
        int kb = s << 5;
        CP_ASYNC16(sA + r0 * APITCH + s0 * 16, Ab + (size_t)r0 * K + kb + s0 * 8);
        CP_ASYNC16(sA + r1 * APITCH + s1 * 16, Ab + (size_t)r1 * K + kb + s1 * 8);
        CP_ASYNC16(sB + r0 * APITCH + s0 * 16, Bb + (size_t)r0 * K + kb + s0 * 8);
        CP_ASYNC16(sB + r1 * APITCH + s1 * 16, Bb + (size_t)r1 * K + kb + s1 * 8);
        CP_COMMIT();
    }

    for (int t = 0; t < KT; t++) {
        CP_WAIT(NSTAGE - 2);
        __syncthreads();
        const int st = t & (NSTAGE - 1);
        const uint32_t sA = sb + st * STAGE_AB, sB = sA + STAGE_A;

        uint32_t a[2][2][4];
        uint32_t b[2][4][4];
        #pragma unroll
        for (int mt = 0; mt < 2; mt++)
            #pragma unroll
            for (int kt = 0; kt < 2; kt++)
                ldm_x4(a[mt][kt][0], a[mt][kt][1], a[mt][kt][2], a[mt][kt][3],
                       sA + (uint32_t)(warpM + mt * 16 + fRow) * APITCH + (kt * 16 + fK) * 2);
        #pragma unroll
        for (int np = 0; np < 4; np++)
            #pragma unroll
            for (int kt = 0; kt < 2; kt++)
                ldm_x4(b[kt][np][0], b[kt][np][1], b[kt][np][2], b[kt][np][3],
                       sB + (uint32_t)(warpN + np * 16 + fRow) * APITCH + (kt * 16 + fK) * 2);

        #pragma unroll
        for (int mt = 0; mt < 2; mt++)
            #pragma unroll
            for (int np = 0; np < 4; np++)
                #pragma unroll
                for (int kt = 0; kt < 2; kt++) {
                    mma16816(acc[mt][np * 2 + 0], a[mt][kt], b[kt][np][0], b[kt][np][2]);
                    mma16816(acc[mt][np * 2 + 1], a[mt][kt], b[kt][np][1], b[kt][np][3]);
                }

        int tn = t + NSTAGE - 1;
        if (tn < KT) {
            int sn = tn & (NSTAGE - 1);
            uint32_t nA = sb + sn * STAGE_AB, nB = nA + STAGE_A;
            int kb = tn << 5;
            CP_ASYNC16(nA + r0 * APITCH + s0 * 16, Ab + (size_t)r0 * K + kb + s0 * 8);
            CP_ASYNC16(nA + r1 * APITCH + s1 * 16, Ab + (size_t)r1 * K + kb + s1 * 8);
            CP_ASYNC16(nB + r0 * APITCH + s0 * 16, Bb + (size_t)r0 * K + kb + s0 * 8);
            CP_ASYNC16(nB + r1 * APITCH + s1 * 16, Bb + (size_t)r1 * K + kb + s1 * 8);
        }
        CP_COMMIT();
    }

    #pragma unroll
    for (int mt = 0; mt < 2; mt++) {
        int rg = bm + warpM + mt * 16 + (lane >> 2);
        #pragma unroll
        for (int nt = 0; nt < 8; nt++) {
            int gcol = bn + warpN + nt * 8 + (lane & 3) * 2;
            float bx = __ldg(&bias[gcol]), by = __ldg(&bias[gcol + 1]);
            float* ac = acc[mt][nt];
            if (OUT_MODE == 0) {
                float2 v0 = make_float2(ac[0] + bx, ac[1] + by);
                float2 v1 = make_float2(ac[2] + bx, ac[3] + by);
                *(float2*)&Cf[(size_t)rg * N + gcol]       = v0;
                *(float2*)&Cf[(size_t)(rg + 8) * N + gcol] = v1;
            } else if (OUT_MODE == 1) {
                float v0 = fmaxf(ac[0] + bx, 0.f), v1 = fmaxf(ac[1] + by, 0.f);
                float v2 = fmaxf(ac[2] + bx, 0.f), v3 = fmaxf(ac[3] + by, 0.f);
                unsigned short h0,h1,h2,h3,l0,l1,l2,l3;
                split1(v0, h0, l0); split1(v1, h1, l1);
                split1(v2, h2, l2); split1(v3, h3, l3);
                unsigned short* D = (unsigned short*)Cs;
                size_t b0r = (size_t)rg * (3 * (size_t)N);
                size_t b1r = (size_t)(rg + 8) * (3 * (size_t)N);
                *(ushort2*)(D + b0r + gcol)       = make_ushort2(h0, h1);
                *(ushort2*)(D + b0r + N + gcol)   = make_ushort2(l0, l1);
                *(ushort2*)(D + b0r + 2*N + gcol) = make_ushort2(h0, h1);
                *(ushort2*)(D + b1r + gcol)       = make_ushort2(h2, h3);
                *(ushort2*)(D + b1r + N + gcol)   = make_ushort2(l2, l3);
                *(ushort2*)(D + b1r + 2*N + gcol) = make_ushort2(h2, h3);
            } else {
                float v0 = ac[0] + bx, v1 = ac[1] + by;
                float v2 = ac[2] + bx, v3 = ac[3] + by;
                unsigned short h0,h1,h2,h3,l0,l1,l2,l3;
                split1(v0, h0, l0); split1(v1, h1, l1);
                split1(v2, h2, l2); split1(v3, h3, l3);
                unsigned short* D = (unsigned short*)Cs;
                size_t b0r = (size_t)rg * (2 * (size_t)N);
                size_t b1r = (size_t)(rg + 8) * (2 * (size_t)N);
                *(ushort2*)(D + b0r + gcol)     = make_ushort2(h0, h1);
                *(ushort2*)(D + b0r + N + gcol) = make_ushort2(l0, l1);
                *(ushort2*)(D + b1r + gcol)     = make_ushort2(h2, h3);
                *(ushort2*)(D + b1r + N + gcol) = make_ushort2(l2, l3);
            }
        }
    }
}

// ===================== tensor-core flash attention (pre-split, pipelined) ====
// Inputs: Q2/K2/V2 2-plane split bf16, row stride 2048 (hi @ h*64, lo @ 1024+h*64).
// 2-stage cp.async double buffer; compute identical to validated R6 path.
// S scaled by 0.125 post-MMA (exact pow2). Output: triple split, stride 3072.
#define APIT 72                           // bf16 per smem row (64 + 8 pad)
#define APLANE (64 * APIT)                // 4608 elems / 9216 B
#define ASTAGE (4 * APLANE)               // Khi,Klo,Vhi,Vlo
#define ATTN_SMEM (2 * ASTAGE * 2)        // 73728 B

template<int CAUSAL>
__global__ __launch_bounds__(128)
void attn_tc(const __nv_bfloat16* __restrict__ Q2, const __nv_bfloat16* __restrict__ K2,
             const __nv_bfloat16* __restrict__ V2, __nv_bfloat16* __restrict__ O2,
             int Sk)
{
    extern __shared__ __nv_bfloat16 smb[];
    const uint32_t uS0 = smem_u32_of(smb);
    const uint32_t uS1 = uS0 + ASTAGE * 2;

    const int h = blockIdx.y;
    const int r0 = blockIdx.x * 64;
    const int tid = threadIdx.x, w = tid >> 5, lane = tid & 31;
    const int fr = lane & 15, fo = (lane >> 4) * 8;

    // loader chunk mapping: cid = i*128 + tid; plane=cid>>9, row=(cid>>3)&63, seg=cid&7
    // per-plane head offsets into the 2-plane tensors
    const uint32_t headoff = (uint32_t)h * 64;

    // ---- stage Q (planes 0,1 of stage1) ----
    #pragma unroll
    for (int i = 0; i < 8; i++) {
        int cid = i * 128 + tid;           // 0..1023 -> planes 0,1
        int plane = cid >> 9, row = (cid >> 3) & 63, seg = cid & 7;
        uint32_t dst = uS1 + (uint32_t)(plane * APLANE + row * APIT + seg * 8) * 2;
        const __nv_bfloat16* src = Q2 + (size_t)(r0 + row) * 2048 + plane * 1024 + headoff + seg * 8;
        CP_ASYNC16(dst, src);
    }
    CP_COMMIT();
    // ---- stage K/V tile 0 into stage0 ----
    #pragma unroll
    for (int i = 0; i < 16; i++) {
        int cid = i * 128 + tid;
        int plane = cid >> 9, row = (cid >> 3) & 63, seg = cid & 7;
        uint32_t dst = uS0 + (uint32_t)(plane * APLANE + row * APIT + seg * 8) * 2;
        const __nv_bfloat16* base = (plane < 2) ? K2 : V2;
        const __nv_bfloat16* src = base + (size_t)row * 2048 + (plane & 1) * 1024 + headoff + seg * 8;
        CP_ASYNC16(dst, src);
    }
    CP_COMMIT();

    CP_WAIT(1);              // Q ready
    __syncthreads();
    uint32_t qh[4][4], ql[4][4];
    #pragma unroll
    for (int kt = 0; kt < 4; kt++) {
        uint32_t off = (uint32_t)(w * 16 + fr) * (APIT * 2) + (kt * 16 + fo) * 2;
        ldm_x4(qh[kt][0], qh[kt][1], qh[kt][2], qh[kt][3], uS0 + ASTAGE * 2 + off);
        ldm_x4(ql[kt][0], ql[kt][1], ql[kt][2], ql[kt][3], uS0 + ASTAGE * 2 + APLANE * 2 + off);
    }
    __syncthreads();         // Q consumed; stage1 free for tile 1

    float o[8][4];
    #pragma unroll
    for (int n = 0; n < 8; n++)
        #pragma unroll
        for (int q = 0; q < 4; q++) o[n][q] = 0.f;
    float m0 = -1e30f, m1 = -1e30f, l0 = 0.f, l1 = 0.f;

    const int nt = CAUSAL ? (blockIdx.x + 1) : (Sk >> 6);
    for (int t = 0; t < nt; t++) {
        // issue next tile into the other stage
        if (t + 1 < nt) {
            const int c1 = (t + 1) * 64;
            const uint32_t uSn = ((t + 1) & 1) ? uS1 : uS0;
            #pragma unroll
            for (int i = 0; i < 16; i++) {
                int cid = i * 128 + tid;
                int plane = cid >> 9, row = (cid >> 3) & 63, seg = cid & 7;
                uint32_t dst = uSn + (uint32_t)(plane * APLANE + row * APIT + seg * 8) * 2;
                const __nv_bfloat16* base = (plane < 2) ? K2 : V2;
                const __nv_bfloat16* src = base + (size_t)(c1 + row) * 2048 + (plane & 1) * 1024 + headoff + seg * 8;
                CP_ASYNC16(dst, src);
            }
        }
        CP_COMMIT();
        CP_WAIT(1);          // tile t ready
        __syncthreads();

        const uint32_t uKhi = ((t & 1) ? uS1 : uS0);
        const uint32_t uKlo = uKhi + APLANE * 2;
        const uint32_t uVhi = uKhi + 2 * APLANE * 2;
        const uint32_t uVlo = uKhi + 3 * APLANE * 2;
        const int c0 = t * 64;

        // ---- S = Q K^T (split 3-pass) ----
        float s[8][4];
        #pragma unroll
        for (int n = 0; n < 8; n++)
            #pragma unroll
            for (int q = 0; q < 4; q++) s[n][q] = 0.f;
        #pragma unroll
        for (int np = 0; np < 4; np++) {
            uint32_t bh[4][4], bl[4][4];
            #pragma unroll
            for (int kt = 0; kt < 4; kt++) {
                uint32_t off = (uint32_t)(np * 16 + fr) * (APIT * 2) + (kt * 16 + fo) * 2;
                ldm_x4(bh[kt][0], bh[kt][1], bh[kt][2], bh[kt][3], uKhi + off);
                ldm_x4(bl[kt][0], bl[kt][1], bl[kt][2], bl[kt][3], uKlo + off);
            }
            #pragma unroll
            for (int kt = 0; kt < 4; kt++) {
                mma16816(s[np*2+0], qh[kt], bh[kt][0], bh[kt][2]);
                mma16816(s[np*2+1], qh[kt], bh[kt][1], bh[kt][3]);
                mma16816(s[np*2+0], ql[kt], bh[kt][0], bh[kt][2]);
                mma16816(s[np*2+1], ql[kt], bh[kt][1], bh[kt][3]);
                mma16816(s[np*2+0], qh[kt], bl[kt][0], bl[kt][2]);
                mma16816(s[np*2+1], qh[kt], bl[kt][1], bl[kt][3]);
            }
        }
        #pragma unroll
        for (int n = 0; n < 8; n++) {
            s[n][0] *= 0.125f; s[n][1] *= 0.125f;
            s[n][2] *= 0.125f; s[n][3] *= 0.125f;
        }

        if (CAUSAL && t == nt - 1) {
            int gr0 = r0 + w * 16 + (lane >> 2);
            int gr1 = gr0 + 8;
            #pragma unroll
            for (int n = 0; n < 8; n++) {
                int col = c0 + n * 8 + (lane & 3) * 2;
                if (col     > gr0) s[n][0] = -1e30f;
                if (col + 1 > gr0) s[n][1] = -1e30f;
                if (col     > gr1) s[n][2] = -1e30f;
                if (col + 1 > gr1) s[n][3] = -1e30f;
            }
        }

        // ---- online softmax ----
        float mx0 = -1e30f, mx1 = -1e30f;
        #pragma unroll
        for (int n = 0; n < 8; n++) {
            mx0 = fmaxf(mx0, fmaxf(s[n][0], s[n][1]));
            mx1 = fmaxf(mx1, fmaxf(s[n][2], s[n][3]));
        }
        mx0 = fmaxf(mx0, __shfl_xor_sync(0xffffffffu, mx0, 1));
        mx0 = fmaxf(mx0, __shfl_xor_sync(0xffffffffu, mx0, 2));
        mx1 = fmaxf(mx1, __shfl_xor_sync(0xffffffffu, mx1, 1));
        mx1 = fmaxf(mx1, __shfl_xor_sync(0xffffffffu, mx1, 2));
        float mn0 = fmaxf(m0, mx0), mn1 = fmaxf(m1, mx1);
        float cor0 = __expf(m0 - mn0), cor1 = __expf(m1 - mn1);
        m0 = mn0; m1 = mn1;
        float ps0 = 0.f, ps1 = 0.f;
        #pragma unroll
        for (int n = 0; n < 8; n++) {
            s[n][0] = __expf(s[n][0] - mn0);
            s[n][1] = __expf(s[n][1] - mn0);
            s[n][2] = __expf(s[n][2] - mn1);
            s[n][3] = __expf(s[n][3] - mn1);
            ps0 += s[n][0] + s[n][1];
            ps1 += s[n][2] + s[n][3];
        }
        ps0 += __shfl_xor_sync(0xffffffffu, ps0, 1);
        ps0 += __shfl_xor_sync(0xffffffffu, ps0, 2);
        ps1 += __shfl_xor_sync(0xffffffffu, ps1, 1);
        ps1 += __shfl_xor_sync(0xffffffffu, ps1, 2);
        l0 = l0 * cor0 + ps0;
        l1 = l1 * cor1 + ps1;
        #pragma unroll
        for (int n = 0; n < 8; n++) {
            o[n][0] *= cor0; o[n][1] *= cor0;
            o[n][2] *= cor1; o[n][3] *= cor1;
        }

        // ---- pack P into A fragments ----
        uint32_t ph[4][4], pl[4][4];
        #pragma unroll
        for (int kt = 0; kt < 4; kt++) {
            int n0 = 2 * kt, n1 = n0 + 1;
            pack_hl(s[n0][0], s[n0][1], ph[kt][0], pl[kt][0]);
            pack_hl(s[n0][2], s[n0][3], ph[kt][1], pl[kt][1]);
            pack_hl(s[n1][0], s[n1][1], ph[kt][2], pl[kt][2]);
            pack_hl(s[n1][2], s[n1][3], ph[kt][3], pl[kt][3]);
        }

        // ---- O += P V (split 3-pass) ----
        #pragma unroll
        for (int dp = 0; dp < 4; dp++) {
            uint32_t vh[4][4], vl[4][4];
            #pragma unroll
            for (int kj = 0; kj < 4; kj++) {
                uint32_t off = (uint32_t)(kj * 16 + fr) * (APIT * 2) + (dp * 16 + fo) * 2;
                ldm_x4t(vh[kj][0], vh[kj][1], vh[kj][2], vh[kj][3], uVhi + off);
                ldm_x4t(vl[kj][0], vl[kj][1], vl[kj][2], vl[kj][3], uVlo + off);
            }
            #pragma unroll
            for (int kj = 0; kj < 4; kj++) {
                mma16816(o[dp*2+0], ph[kj], vh[kj][0], vh[kj][1]);
                mma16816(o[dp*2+1], ph[kj], vh[kj][2], vh[kj][3]);
                mma16816(o[dp*2+0], pl[kj], vh[kj][0], vh[kj][1]);
                mma16816(o[dp*2+1], pl[kj], vh[kj][2], vh[kj][3]);
                mma16816(o[dp*2+0], ph[kj], vl[kj][0], vl[kj][1]);
                mma16816(o[dp*2+1], ph[kj], vl[kj][2], vl[kj][3]);
            }
        }
        __syncthreads();     // tile t consumed; its buffer becomes t+2's target
    }

    // ---- epilogue: triple split layout [hi | lo | hi], row stride 3072 ----
    float inv0 = 1.f / l0, inv1 = 1.f / l1;
    int gr0 = r0 + w * 16 + (lane >> 2);
    unsigned short* D = (unsigned short*)O2;
    #pragma unroll
    for (int n = 0; n < 8; n++) {
        int col = h * 64 + n * 8 + (lane & 3) * 2;
        float v0 = o[n][0] * inv0, v1 = o[n][1] * inv0;
        float v2 = o[n][2] * inv1, v3 = o[n][3] * inv1;
        unsigned short h0,h1,h2,h3,l0s,l1s,l2s,l3s;
        split1(v0, h0, l0s); split1(v1, h1, l1s);
        split1(v2, h2, l2s); split1(v3, h3, l3s);
        size_t b0r = (size_t)gr0 * 3072;
        size_t b1r = (size_t)(gr0 + 8) * 3072;
        *(ushort2*)(D + b0r + col)        = make_ushort2(h0, h1);
        *(ushort2*)(D + b0r + 1024 + col) = make_ushort2(l0s, l1s);
        *(ushort2*)(D + b0r + 2048 + col) = make_ushort2(h0, h1);
        *(ushort2*)(D + b1r + col)        = make_ushort2(h2, h3);
        *(ushort2*)(D + b1r + 1024 + col) = make_ushort2(l2s, l3s);
        *(ushort2*)(D + b1r + 2048 + col) = make_ushort2(h2, h3);
    }
}

// ===================== launch =====================
static inline dim3 split_grid(int M, int K) { return dim3((M * (K / 4) + 255) / 256); }

extern "C" void kernel_launch(void* const* d_in, const int* in_sizes, int n_in,
                              void* d_out, int out_size)
{
    const float* wemb = (const float*)d_in[0];
    const float* pemb = (const float*)d_in[1];
    const float* Wq_m = (const float*)d_in[2];
    const float* bq_m = (const float*)d_in[3];
    const float* Wk_m = (const float*)d_in[4];
    const float* bk_m = (const float*)d_in[5];
    const float* Wv_m = (const float*)d_in[6];
    const float* bv_m = (const float*)d_in[7];
    const float* Wq_c = (const float*)d_in[8];
    const float* bq_c = (const float*)d_in[9];
    const float* Wk_c = (const float*)d_in[10];
    const float* bk_c = (const float*)d_in[11];
    const float* Wv_c = (const float*)d_in[12];
    const float* bv_c = (const float*)d_in[13];
    const float* W1   = (const float*)d_in[14];
    const float* b1   = (const float*)d_in[15];
    const float* W2   = (const float*)d_in[16];
    const float* b2   = (const float*)d_in[17];
    float* out = (float*)d_out;

    __nv_bfloat16 *Q2m, *K2m, *V2m, *Q2c, *K2c, *V2c;
    __nv_bfloat16 *wemb2, *pemb2, *word2, *cross2;
    __nv_bfloat16 *Wqm2, *Wkm2, *Wvm2, *Wqc2, *Wkc2, *Wvc2, *W12, *W22, *Hf2;
    cudaGetSymbolAddress((void**)&Q2m, g_Q2m);
    cudaGetSymbolAddress((void**)&K2m, g_K2m);
    cudaGetSymbolAddress((void**)&V2m, g_V2m);
    cudaGetSymbolAddress((void**)&Q2c, g_Q2c);
    cudaGetSymbolAddress((void**)&K2c, g_K2c);
    cudaGetSymbolAddress((void**)&V2c, g_V2c);
    cudaGetSymbolAddress((void**)&wemb2, g_wemb2);
    cudaGetSymbolAddress((void**)&pemb2, g_pemb2);
    cudaGetSymbolAddress((void**)&word2, g_word2);
    cudaGetSymbolAddress((void**)&cross2, g_cross2);
    cudaGetSymbolAddress((void**)&Wqm2, g_Wqm2);
    cudaGetSymbolAddress((void**)&Wkm2, g_Wkm2);
    cudaGetSymbolAddress((void**)&Wvm2, g_Wvm2);
    cudaGetSymbolAddress((void**)&Wqc2, g_Wqc2);
    cudaGetSymbolAddress((void**)&Wkc2, g_Wkc2);
    cudaGetSymbolAddress((void**)&Wvc2, g_Wvc2);
    cudaGetSymbolAddress((void**)&W12, g_W12);
    cudaGetSymbolAddress((void**)&W22, g_W22);
    cudaGetSymbolAddress((void**)&Hf2, g_Hf2);

    cudaFuncSetAttribute((const void*)gemm_tc<0>,
                         cudaFuncAttributeMaxDynamicSharedMemorySize, GEMM_SMEM);
    cudaFuncSetAttribute((const void*)gemm_tc<1>,
                         cudaFuncAttributeMaxDynamicSharedMemorySize, GEMM_SMEM);
    cudaFuncSetAttribute((const void*)gemm_tc<2>,
                         cudaFuncAttributeMaxDynamicSharedMemorySize, GEMM_SMEM);
    cudaFuncSetAttribute((const void*)attn_tc<0>,
                         cudaFuncAttributeMaxDynamicSharedMemorySize, ATTN_SMEM);
    cudaFuncSetAttribute((const void*)attn_tc<1>,
                         cudaFuncAttributeMaxDynamicSharedMemorySize, ATTN_SMEM);

    // ---- split weights + inputs ----
    split_k<0><<<split_grid(2048, 1024), 256>>>(wemb, wemb2, 2048, 1024);
    split_k<0><<<split_grid(1024, 1024), 256>>>(pemb, pemb2, 1024, 1024);
    split_k<1><<<split_grid(1024, 1024), 256>>>(Wq_m, Wqm2, 1024, 1024);
    split_k<1><<<split_grid(1024, 1024), 256>>>(Wk_m, Wkm2, 1024, 1024);
    split_k<1><<<split_grid(1024, 1024), 256>>>(Wv_m, Wvm2, 1024, 1024);
    split_k<1><<<split_grid(1024, 1024), 256>>>(Wq_c, Wqc2, 1024, 1024);
    split_k<1><<<split_grid(1024, 1024), 256>>>(Wk_c, Wkc2, 1024, 1024);
    split_k<1><<<split_grid(1024, 1024), 256>>>(Wv_c, Wvc2, 1024, 1024);
    split_k<1><<<split_grid(4096, 1024), 256>>>(W1, W12, 4096, 1024);
    split_k<1><<<split_grid(1024, 4096), 256>>>(W2, W22, 1024, 4096);

    // ---- self-attn QKV projections -> 2-plane split bf16 ----
    gemm_tc<2><<<dim3(8, 16), 256, GEMM_SMEM>>>(wemb2, Wqm2, bq_m, nullptr, Q2m, 2048, 1024, 3072);
    gemm_tc<2><<<dim3(8, 16), 256, GEMM_SMEM>>>(wemb2, Wkm2, bk_m, nullptr, K2m, 2048, 1024, 3072);
    gemm_tc<2><<<dim3(8, 16), 256, GEMM_SMEM>>>(wemb2, Wvm2, bv_m, nullptr, V2m, 2048, 1024, 3072);

    // ---- causal self-attention (writes word2 triple-split directly) ----
    attn_tc<1><<<dim3(32, 16), 128, ATTN_SMEM>>>(Q2m, K2m, V2m, word2, 2048);

    // ---- cross projections ----
    gemm_tc<2><<<dim3(8, 16), 256, GEMM_SMEM>>>(word2, Wqc2, bq_c, nullptr, Q2c, 2048, 1024, 3072);
    gemm_tc<2><<<dim3(8, 8),  256, GEMM_SMEM>>>(pemb2, Wkc2, bk_c, nullptr, K2c, 1024, 1024, 3072);
    gemm_tc<2><<<dim3(8, 8),  256, GEMM_SMEM>>>(pemb2, Wvc2, bv_c, nullptr, V2c, 1024, 1024, 3072);

    // ---- cross attention (writes cross2 triple-split directly) ----
    attn_tc<0><<<dim3(32, 16), 128, ATTN_SMEM>>>(Q2c, K2c, V2c, cross2, 1024);

    // ---- FFN ----
    gemm_tc<1><<<dim3(32, 16), 256, GEMM_SMEM>>>(cross2, W12, b1, nullptr, Hf2, 2048, 4096, 3072);
    gemm_tc<0><<<dim3(8, 16),  256, GEMM_SMEM>>>(Hf2, W22, b2, out, nullptr, 2048, 1024, 12288);
}

// round 8
// speedup vs baseline: 2.4997x; 1.0217x over previous
#include <cuda_runtime.h>
#include <cuda_bf16.h>
#include <math.h>
#include <stdint.h>

// ===================== scratch (static; no allocations) =====================
__device__ __nv_bfloat16 g_Q2m[2048*2048];
__device__ __nv_bfloat16 g_K2m[2048*2048];
__device__ __nv_bfloat16 g_V2m[2048*2048];
__device__ __nv_bfloat16 g_Q2c[2048*2048];
__device__ __nv_bfloat16 g_K2c[1024*2048];
__device__ __nv_bfloat16 g_V2c[1024*2048];

__device__ __nv_bfloat16 g_wemb2 [2048*3072];
__device__ __nv_bfloat16 g_pemb2 [1024*3072];
__device__ __nv_bfloat16 g_word2 [2048*3072];
__device__ __nv_bfloat16 g_cross2[2048*3072];
__device__ __nv_bfloat16 g_Wqm2[1024*3072];
__device__ __nv_bfloat16 g_Wkm2[1024*3072];
__device__ __nv_bfloat16 g_Wvm2[1024*3072];
__device__ __nv_bfloat16 g_Wqc2[1024*3072];
__device__ __nv_bfloat16 g_Wkc2[1024*3072];
__device__ __nv_bfloat16 g_Wvc2[1024*3072];
__device__ __nv_bfloat16 g_W12 [4096*3072];
__device__ __nv_bfloat16 g_W22 [1024*12288];
__device__ __nv_bfloat16 g_Hf2 [2048*12288];

// ===================== PTX helpers =====================
__device__ __forceinline__ uint32_t smem_u32_of(const void* p) {
    uint32_t a;
    asm("{ .reg .u64 t; cvta.to.shared.u64 t, %1; cvt.u32.u64 %0, t; }" : "=r"(a) : "l"(p));
    return a;
}
#define CP_ASYNC16(sm, gp) \
    asm volatile("cp.async.cg.shared.global [%0], [%1], 16;" :: "r"(sm), "l"(gp))
#define CP_COMMIT() asm volatile("cp.async.commit_group;" ::: "memory")
#define CP_WAIT(n)  asm volatile("cp.async.wait_group %0;" :: "n"(n) : "memory")

__device__ __forceinline__ void ldm_x4(uint32_t& r0, uint32_t& r1, uint32_t& r2, uint32_t& r3,
                                       uint32_t addr) {
    asm volatile("ldmatrix.sync.aligned.m8n8.x4.shared.b16 {%0,%1,%2,%3}, [%4];"
                 : "=r"(r0), "=r"(r1), "=r"(r2), "=r"(r3) : "r"(addr));
}
__device__ __forceinline__ void ldm_x4t(uint32_t& r0, uint32_t& r1, uint32_t& r2, uint32_t& r3,
                                        uint32_t addr) {
    asm volatile("ldmatrix.sync.aligned.m8n8.x4.trans.shared.b16 {%0,%1,%2,%3}, [%4];"
                 : "=r"(r0), "=r"(r1), "=r"(r2), "=r"(r3) : "r"(addr));
}
__device__ __forceinline__ void mma16816(float* c, const uint32_t* a,
                                         uint32_t b0, uint32_t b1) {
    asm volatile("mma.sync.aligned.m16n8k16.row.col.f32.bf16.bf16.f32 "
                 "{%0,%1,%2,%3}, {%4,%5,%6,%7}, {%8,%9}, {%0,%1,%2,%3};"
                 : "+f"(c[0]), "+f"(c[1]), "+f"(c[2]), "+f"(c[3])
                 : "r"(a[0]), "r"(a[1]), "r"(a[2]), "r"(a[3]), "r"(b0), "r"(b1));
}

// ===================== split helpers =====================
__device__ __forceinline__ void split1(float v, unsigned short& h, unsigned short& l) {
    __nv_bfloat16 hb = __float2bfloat16(v);
    __nv_bfloat16 lb = __float2bfloat16(v - __bfloat162float(hb));
    h = __bfloat16_as_ushort(hb);
    l = __bfloat16_as_ushort(lb);
}
__device__ __forceinline__ void pack_hl(float a, float b, uint32_t& hi, uint32_t& lo) {
    unsigned short ha, la, hb, lb;
    split1(a, ha, la);
    split1(b, hb, lb);
    hi = ((uint32_t)hb << 16) | ha;
    lo = ((uint32_t)lb << 16) | la;
}

// ===================== batched split kernel (10 jobs, 1 launch) =============
struct SplitJobs {
    const float*  src[10];
    __nv_bfloat16* dst[10];
    int K[10];
    int mode[10];     // 0: [hi,lo,hi]  1: [hi,hi,lo]
    int cum[11];      // cumulative 4-elem chunk counts
};

__global__ __launch_bounds__(256)
void split_all(SplitJobs J)
{
    int cid = blockIdx.x * 256 + threadIdx.x;
    if (cid >= J.cum[10]) return;
    int j = 0;
    #pragma unroll
    for (int t = 0; t < 10; t++) if (cid >= J.cum[t + 1]) j = t + 1;
    int local = cid - J.cum[j];
    int K = J.K[j], kq = K >> 2;
    int m = local / kq;
    int k4 = (local - m * kq) << 2;
    float4 v = *(const float4*)(J.src[j] + (size_t)m * K + k4);
    unsigned short h0,h1,h2,h3,l0,l1,l2,l3;
    split1(v.x, h0, l0); split1(v.y, h1, l1);
    split1(v.z, h2, l2); split1(v.w, h3, l3);
    ushort4 H = make_ushort4(h0, h1, h2, h3);
    ushort4 L = make_ushort4(l0, l1, l2, l3);
    unsigned short* D = (unsigned short*)J.dst[j];
    size_t b = (size_t)m * (3 * (size_t)K);
    if (J.mode[j] == 0) {
        *(ushort4*)(D + b + k4)       = H;
        *(ushort4*)(D + b + K + k4)   = L;
        *(ushort4*)(D + b + 2*K + k4) = H;
    } else {
        *(ushort4*)(D + b + k4)       = H;
        *(ushort4*)(D + b + K + k4)   = H;
        *(ushort4*)(D + b + 2*K + k4) = L;
    }
}

// ===================== mma.sync bf16 GEMM (validated R5) =====================
#define NSTAGE   4
#define APITCH   80
#define STAGE_A  (128 * APITCH)
#define STAGE_AB (2 * STAGE_A)
#define GEMM_SMEM (NSTAGE * STAGE_AB)

template<int OUT_MODE>
__global__ __launch_bounds__(256, 1)
void gemm_tc(const __nv_bfloat16* __restrict__ A, const __nv_bfloat16* __restrict__ B,
             const float* __restrict__ bias, float* __restrict__ Cf,
             __nv_bfloat16* __restrict__ Cs, int M, int N, int K)
{
    extern __shared__ char smem[];
    const uint32_t sb = smem_u32_of(smem);
    const int tid = threadIdx.x, warp = tid >> 5, lane = tid & 31;
    const int warpM = (warp >> 1) * 32, warpN = (warp & 1) * 64;
    const int bm = blockIdx.y * 128, bn = blockIdx.x * 128;
    const int KT = K >> 5;

    const int r0 = tid >> 2,        s0 = (tid & 3);
    const int r1 = r0 + 64,         s1 = s0;
    const __nv_bfloat16* Ab = A + (size_t)bm * K;
    const __nv_bfloat16* Bb = B + (size_t)bn * K;

    const int fRow = lane & 15;
    const int fK   = (lane >> 4) * 8;

    float acc[2][8][4];
    #pragma unroll
    for (int i = 0; i < 2; i++)
        #pragma unroll
        for (int j = 0; j < 8; j++)
            #pragma unroll
            for (int q = 0; q < 4; q++) acc[i][j][q] = 0.f;

    #pragma unroll
    for (int s = 0; s < NSTAGE - 1; s++) {
        uint32_t sA = sb + s * STAGE_AB, sB = sA + STAGE_A;
        int kb = s << 5;
        CP_ASYNC16(sA + r0 * APITCH + s0 * 16, Ab + (size_t)r0 * K + kb + s0 * 8);
        CP_ASYNC16(sA + r1 * APITCH + s1 * 16, Ab + (size_t)r1 * K + kb + s1 * 8);
        CP_ASYNC16(sB + r0 * APITCH + s0 * 16, Bb + (size_t)r0 * K + kb + s0 * 8);
        CP_ASYNC16(sB + r1 * APITCH + s1 * 16, Bb + (size_t)r1 * K + kb + s1 * 8);
        CP_COMMIT();
    }

    for (int t = 0; t < KT; t++) {
        CP_WAIT(NSTAGE - 2);
        __syncthreads();
        const int st = t & (NSTAGE - 1);
        const uint32_t sA = sb + st * STAGE_AB, sB = sA + STAGE_A;

        uint32_t a[2][2][4];
        uint32_t b[2][4][4];
        #pragma unroll
        for (int mt = 0; mt < 2; mt++)
            #pragma unroll
            for (int kt = 0; kt < 2; kt++)
                ldm_x4(a[mt][kt][0], a[mt][kt][1], a[mt][kt][2], a[mt][kt][3],
                       sA + (uint32_t)(warpM + mt * 16 + fRow) * APITCH + (kt * 16 + fK) * 2);
        #pragma unroll
        for (int np = 0; np < 4; np++)
            #pragma unroll
            for (int kt = 0; kt < 2; kt++)
                ldm_x4(b[kt][np][0], b[kt][np][1], b[kt][np][2], b[kt][np][3],
                       sB + (uint32_t)(warpN + np * 16 + fRow) * APITCH + (kt * 16 + fK) * 2);

        #pragma unroll
        for (int mt = 0; mt < 2; mt++)
            #pragma unroll
            for (int np = 0; np < 4; np++)
                #pragma unroll
                for (int kt = 0; kt < 2; kt++) {
                    mma16816(acc[mt][np * 2 + 0], a[mt][kt], b[kt][np][0], b[kt][np][2]);
                    mma16816(acc[mt][np * 2 + 1], a[mt][kt], b[kt][np][1], b[kt][np][3]);
                }

        int tn = t + NSTAGE - 1;
        if (tn < KT) {
            int sn = tn & (NSTAGE - 1);
            uint32_t nA = sb + sn * STAGE_AB, nB = nA + STAGE_A;
            int kb = tn << 5;
            CP_ASYNC16(nA + r0 * APITCH + s0 * 16, Ab + (size_t)r0 * K + kb + s0 * 8);
            CP_ASYNC16(nA + r1 * APITCH + s1 * 16, Ab + (size_t)r1 * K + kb + s1 * 8);
            CP_ASYNC16(nB + r0 * APITCH + s0 * 16, Bb + (size_t)r0 * K + kb + s0 * 8);
            CP_ASYNC16(nB + r1 * APITCH + s1 * 16, Bb + (size_t)r1 * K + kb + s1 * 8);
        }
        CP_COMMIT();
    }

    #pragma unroll
    for (int mt = 0; mt < 2; mt++) {
        int rg = bm + warpM + mt * 16 + (lane >> 2);
        #pragma unroll
        for (int nt = 0; nt < 8; nt++) {
            int gcol = bn + warpN + nt * 8 + (lane & 3) * 2;
            float bx = __ldg(&bias[gcol]), by = __ldg(&bias[gcol + 1]);
            float* ac = acc[mt][nt];
            if (OUT_MODE == 0) {
                float2 v0 = make_float2(ac[0] + bx, ac[1] + by);
                float2 v1 = make_float2(ac[2] + bx, ac[3] + by);
                *(float2*)&Cf[(size_t)rg * N + gcol]       = v0;
                *(float2*)&Cf[(size_t)(rg + 8) * N + gcol] = v1;
            } else if (OUT_MODE == 1) {
                float v0 = fmaxf(ac[0] + bx, 0.f), v1 = fmaxf(ac[1] + by, 0.f);
                float v2 = fmaxf(ac[2] + bx, 0.f), v3 = fmaxf(ac[3] + by, 0.f);
                unsigned short h0,h1,h2,h3,l0,l1,l2,l3;
                split1(v0, h0, l0); split1(v1, h1, l1);
                split1(v2, h2, l2); split1(v3, h3, l3);
                unsigned short* D = (unsigned short*)Cs;
                size_t b0r = (size_t)rg * (3 * (size_t)N);
                size_t b1r = (size_t)(rg + 8) * (3 * (size_t)N);
                *(ushort2*)(D + b0r + gcol)       = make_ushort2(h0, h1);
                *(ushort2*)(D + b0r + N + gcol)   = make_ushort2(l0, l1);
                *(ushort2*)(D + b0r + 2*N + gcol) = make_ushort2(h0, h1);
                *(ushort2*)(D + b1r + gcol)       = make_ushort2(h2, h3);
                *(ushort2*)(D + b1r + N + gcol)   = make_ushort2(l2, l3);
                *(ushort2*)(D + b1r + 2*N + gcol) = make_ushort2(h2, h3);
            } else {
                float v0 = ac[0] + bx, v1 = ac[1] + by;
                float v2 = ac[2] + bx, v3 = ac[3] + by;
                unsigned short h0,h1,h2,h3,l0,l1,l2,l3;
                split1(v0, h0, l0); split1(v1, h1, l1);
                split1(v2, h2, l2); split1(v3, h3, l3);
                unsigned short* D = (unsigned short*)Cs;
                size_t b0r = (size_t)rg * (2 * (size_t)N);
                size_t b1r = (size_t)(rg + 8) * (2 * (size_t)N);
                *(ushort2*)(D + b0r + gcol)     = make_ushort2(h0, h1);
                *(ushort2*)(D + b0r + N + gcol) = make_ushort2(l0, l1);
                *(ushort2*)(D + b1r + gcol)     = make_ushort2(h2, h3);
                *(ushort2*)(D + b1r + N + gcol) = make_ushort2(l2, l3);
            }
        }
    }
}

// ===================== tensor-core flash attention (pre-split, pipelined) ====
#define APIT 72
#define APLANE (64 * APIT)
#define ASTAGE (4 * APLANE)
#define ATTN_SMEM (2 * ASTAGE * 2)

template<int CAUSAL>
__global__ __launch_bounds__(128)
void attn_tc(const __nv_bfloat16* __restrict__ Q2, const __nv_bfloat16* __restrict__ K2,
             const __nv_bfloat16* __restrict__ V2, __nv_bfloat16* __restrict__ O2,
             int Sk)
{
    extern __shared__ __nv_bfloat16 smb[];
    const uint32_t uS0 = smem_u32_of(smb);
    const uint32_t uS1 = uS0 + ASTAGE * 2;

    const int h = blockIdx.y;
    // LPT scheduling for causal: heaviest row-blocks launch first
    const int bx = CAUSAL ? ((int)gridDim.x - 1 - (int)blockIdx.x) : (int)blockIdx.x;
    const int r0 = bx * 64;
    const int tid = threadIdx.x, w = tid >> 5, lane = tid & 31;
    const int fr = lane & 15, fo = (lane >> 4) * 8;
    const uint32_t headoff = (uint32_t)h * 64;

    // ---- stage Q (planes 0,1 of stage1) ----
    #pragma unroll
    for (int i = 0; i < 8; i++) {
        int cid = i * 128 + tid;
        int plane = cid >> 9, row = (cid >> 3) & 63, seg = cid & 7;
        uint32_t dst = uS1 + (uint32_t)(plane * APLANE + row * APIT + seg * 8) * 2;
        const __nv_bfloat16* src = Q2 + (size_t)(r0 + row) * 2048 + plane * 1024 + headoff + seg * 8;
        CP_ASYNC16(dst, src);
    }
    CP_COMMIT();
    // ---- stage K/V tile 0 into stage0 ----
    #pragma unroll
    for (int i = 0; i < 16; i++) {
        int cid = i * 128 + tid;
        int plane = cid >> 9, row = (cid >> 3) & 63, seg = cid & 7;
        uint32_t dst = uS0 + (uint32_t)(plane * APLANE + row * APIT + seg * 8) * 2;
        const __nv_bfloat16* base = (plane < 2) ? K2 : V2;
        const __nv_bfloat16* src = base + (size_t)row * 2048 + (plane & 1) * 1024 + headoff + seg * 8;
        CP_ASYNC16(dst, src);
    }
    CP_COMMIT();

    CP_WAIT(1);
    __syncthreads();
    uint32_t qh[4][4], ql[4][4];
    #pragma unroll
    for (int kt = 0; kt < 4; kt++) {
        uint32_t off = (uint32_t)(w * 16 + fr) * (APIT * 2) + (kt * 16 + fo) * 2;
        ldm_x4(qh[kt][0], qh[kt][1], qh[kt][2], qh[kt][3], uS0 + ASTAGE * 2 + off);
        ldm_x4(ql[kt][0], ql[kt][1], ql[kt][2], ql[kt][3], uS0 + ASTAGE * 2 + APLANE * 2 + off);
    }
    __syncthreads();

    float o[8][4];
    #pragma unroll
    for (int n = 0; n < 8; n++)
        #pragma unroll
        for (int q = 0; q < 4; q++) o[n][q] = 0.f;
    float m0 = -1e30f, m1 = -1e30f, l0 = 0.f, l1 = 0.f;

    const int nt = CAUSAL ? (bx + 1) : (Sk >> 6);
    for (int t = 0; t < nt; t++) {
        if (t + 1 < nt) {
            const int c1 = (t + 1) * 64;
            const uint32_t uSn = ((t + 1) & 1) ? uS1 : uS0;
            #pragma unroll
            for (int i = 0; i < 16; i++) {
                int cid = i * 128 + tid;
                int plane = cid >> 9, row = (cid >> 3) & 63, seg = cid & 7;
                uint32_t dst = uSn + (uint32_t)(plane * APLANE + row * APIT + seg * 8) * 2;
                const __nv_bfloat16* base = (plane < 2) ? K2 : V2;
                const __nv_bfloat16* src = base + (size_t)(c1 + row) * 2048 + (plane & 1) * 1024 + headoff + seg * 8;
                CP_ASYNC16(dst, src);
            }
        }
        CP_COMMIT();
        CP_WAIT(1);
        __syncthreads();

        const uint32_t uKhi = ((t & 1) ? uS1 : uS0);
        const uint32_t uKlo = uKhi + APLANE * 2;
        const uint32_t uVhi = uKhi + 2 * APLANE * 2;
        const uint32_t uVlo = uKhi + 3 * APLANE * 2;
        const int c0 = t * 64;

        float s[8][4];
        #pragma unroll
        for (int n = 0; n < 8; n++)
            #pragma unroll
            for (int q = 0; q < 4; q++) s[n][q] = 0.f;
        #pragma unroll
        for (int np = 0; np < 4; np++) {
            uint32_t bh[4][4], bl[4][4];
            #pragma unroll
            for (int kt = 0; kt < 4; kt++) {
                uint32_t off = (uint32_t)(np * 16 + fr) * (APIT * 2) + (kt * 16 + fo) * 2;
                ldm_x4(bh[kt][0], bh[kt][1], bh[kt][2], bh[kt][3], uKhi + off);
                ldm_x4(bl[kt][0], bl[kt][1], bl[kt][2], bl[kt][3], uKlo + off);
            }
            #pragma unroll
            for (int kt = 0; kt < 4; kt++) {
                mma16816(s[np*2+0], qh[kt], bh[kt][0], bh[kt][2]);
                mma16816(s[np*2+1], qh[kt], bh[kt][1], bh[kt][3]);
                mma16816(s[np*2+0], ql[kt], bh[kt][0], bh[kt][2]);
                mma16816(s[np*2+1], ql[kt], bh[kt][1], bh[kt][3]);
                mma16816(s[np*2+0], qh[kt], bl[kt][0], bl[kt][2]);
                mma16816(s[np*2+1], qh[kt], bl[kt][1], bl[kt][3]);
            }
        }
        #pragma unroll
        for (int n = 0; n < 8; n++) {
            s[n][0] *= 0.125f; s[n][1] *= 0.125f;
            s[n][2] *= 0.125f; s[n][3] *= 0.125f;
        }

        if (CAUSAL && t == nt - 1) {
            int gr0 = r0 + w * 16 + (lane >> 2);
            int gr1 = gr0 + 8;
            #pragma unroll
            for (int n = 0; n < 8; n++) {
                int col = c0 + n * 8 + (lane & 3) * 2;
                if (col     > gr0) s[n][0] = -1e30f;
                if (col + 1 > gr0) s[n][1] = -1e30f;
                if (col     > gr1) s[n][2] = -1e30f;
                if (col + 1 > gr1) s[n][3] = -1e30f;
            }
        }

        float mx0 = -1e30f, mx1 = -1e30f;
        #pragma unroll
        for (int n = 0; n < 8; n++) {
            mx0 = fmaxf(mx0, fmaxf(s[n][0], s[n][1]));
            mx1 = fmaxf(mx1, fmaxf(s[n][2], s[n][3]));
        }
        mx0 = fmaxf(mx0, __shfl_xor_sync(0xffffffffu, mx0, 1));
        mx0 = fmaxf(mx0, __shfl_xor_sync(0xffffffffu, mx0, 2));
        mx1 = fmaxf(mx1, __shfl_xor_sync(0xffffffffu, mx1, 1));
        mx1 = fmaxf(mx1, __shfl_xor_sync(0xffffffffu, mx1, 2));
        float mn0 = fmaxf(m0, mx0), mn1 = fmaxf(m1, mx1);
        float cor0 = __expf(m0 - mn0), cor1 = __expf(m1 - mn1);
        m0 = mn0; m1 = mn1;
        float ps0 = 0.f, ps1 = 0.f;
        #pragma unroll
        for (int n = 0; n < 8; n++) {
            s[n][0] = __expf(s[n][0] - mn0);
            s[n][1] = __expf(s[n][1] - mn0);
            s[n][2] = __expf(s[n][2] - mn1);
            s[n][3] = __expf(s[n][3] - mn1);
            ps0 += s[n][0] + s[n][1];
            ps1 += s[n][2] + s[n][3];
        }
        ps0 += __shfl_xor_sync(0xffffffffu, ps0, 1);
        ps0 += __shfl_xor_sync(0xffffffffu, ps0, 2);
        ps1 += __shfl_xor_sync(0xffffffffu, ps1, 1);
        ps1 += __shfl_xor_sync(0xffffffffu, ps1, 2);
        l0 = l0 * cor0 + ps0;
        l1 = l1 * cor1 + ps1;
        #pragma unroll
        for (int n = 0; n < 8; n++) {
            o[n][0] *= cor0; o[n][1] *= cor0;
            o[n][2] *= cor1; o[n][3] *= cor1;
        }

        uint32_t ph[4][4], pl[4][4];
        #pragma unroll
        for (int kt = 0; kt < 4; kt++) {
            int n0 = 2 * kt, n1 = n0 + 1;
            pack_hl(s[n0][0], s[n0][1], ph[kt][0], pl[kt][0]);
            pack_hl(s[n0][2], s[n0][3], ph[kt][1], pl[kt][1]);
            pack_hl(s[n1][0], s[n1][1], ph[kt][2], pl[kt][2]);
            pack_hl(s[n1][2], s[n1][3], ph[kt][3], pl[kt][3]);
        }

        #pragma unroll
        for (int dp = 0; dp < 4; dp++) {
            uint32_t vh[4][4], vl[4][4];
            #pragma unroll
            for (int kj = 0; kj < 4; kj++) {
                uint32_t off = (uint32_t)(kj * 16 + fr) * (APIT * 2) + (dp * 16 + fo) * 2;
                ldm_x4t(vh[kj][0], vh[kj][1], vh[kj][2], vh[kj][3], uVhi + off);
                ldm_x4t(vl[kj][0], vl[kj][1], vl[kj][2], vl[kj][3], uVlo + off);
            }
            #pragma unroll
            for (int kj = 0; kj < 4; kj++) {
                mma16816(o[dp*2+0], ph[kj], vh[kj][0], vh[kj][1]);
                mma16816(o[dp*2+1], ph[kj], vh[kj][2], vh[kj][3]);
                mma16816(o[dp*2+0], pl[kj], vh[kj][0], vh[kj][1]);
                mma16816(o[dp*2+1], pl[kj], vh[kj][2], vh[kj][3]);
                mma16816(o[dp*2+0], ph[kj], vl[kj][0], vl[kj][1]);
                mma16816(o[dp*2+1], ph[kj], vl[kj][2], vl[kj][3]);
            }
        }
        __syncthreads();
    }

    float inv0 = 1.f / l0, inv1 = 1.f / l1;
    int gr0 = r0 + w * 16 + (lane >> 2);
    unsigned short* D = (unsigned short*)O2;
    #pragma unroll
    for (int n = 0; n < 8; n++) {
        int col = h * 64 + n * 8 + (lane & 3) * 2;
        float v0 = o[n][0] * inv0, v1 = o[n][1] * inv0;
        float v2 = o[n][2] * inv1, v3 = o[n][3] * inv1;
        unsigned short h0,h1,h2,h3,l0s,l1s,l2s,l3s;
        split1(v0, h0, l0s); split1(v1, h1, l1s);
        split1(v2, h2, l2s); split1(v3, h3, l3s);
        size_t b0r = (size_t)gr0 * 3072;
        size_t b1r = (size_t)(gr0 + 8) * 3072;
        *(ushort2*)(D + b0r + col)        = make_ushort2(h0, h1);
        *(ushort2*)(D + b0r + 1024 + col) = make_ushort2(l0s, l1s);
        *(ushort2*)(D + b0r + 2048 + col) = make_ushort2(h0, h1);
        *(ushort2*)(D + b1r + col)        = make_ushort2(h2, h3);
        *(ushort2*)(D + b1r + 1024 + col) = make_ushort2(l2s, l3s);
        *(ushort2*)(D + b1r + 2048 + col) = make_ushort2(h2, h3);
    }
}

// ===================== launch =====================
extern "C" void kernel_launch(void* const* d_in, const int* in_sizes, int n_in,
                              void* d_out, int out_size)
{
    const float* wemb = (const float*)d_in[0];
    const float* pemb = (const float*)d_in[1];
    const float* Wq_m = (const float*)d_in[2];
    const float* bq_m = (const float*)d_in[3];
    const float* Wk_m = (const float*)d_in[4];
    const float* bk_m = (const float*)d_in[5];
    const float* Wv_m = (const float*)d_in[6];
    const float* bv_m = (const float*)d_in[7];
    const float* Wq_c = (const float*)d_in[8];
    const float* bq_c = (const float*)d_in[9];
    const float* Wk_c = (const float*)d_in[10];
    const float* bk_c = (const float*)d_in[11];
    const float* Wv_c = (const float*)d_in[12];
    const float* bv_c = (const float*)d_in[13];
    const float* W1   = (const float*)d_in[14];
    const float* b1   = (const float*)d_in[15];
    const float* W2   = (const float*)d_in[16];
    const float* b2   = (const float*)d_in[17];
    float* out = (float*)d_out;

    __nv_bfloat16 *Q2m, *K2m, *V2m, *Q2c, *K2c, *V2c;
    __nv_bfloat16 *wemb2, *pemb2, *word2, *cross2;
    __nv_bfloat16 *Wqm2, *Wkm2, *Wvm2, *Wqc2, *Wkc2, *Wvc2, *W12, *W22, *Hf2;
    cudaGetSymbolAddress((void**)&Q2m, g_Q2m);
    cudaGetSymbolAddress((void**)&K2m, g_K2m);
    cudaGetSymbolAddress((void**)&V2m, g_V2m);
    cudaGetSymbolAddress((void**)&Q2c, g_Q2c);
    cudaGetSymbolAddress((void**)&K2c, g_K2c);
    cudaGetSymbolAddress((void**)&V2c, g_V2c);
    cudaGetSymbolAddress((void**)&wemb2, g_wemb2);
    cudaGetSymbolAddress((void**)&pemb2, g_pemb2);
    cudaGetSymbolAddress((void**)&word2, g_word2);
    cudaGetSymbolAddress((void**)&cross2, g_cross2);
    cudaGetSymbolAddress((void**)&Wqm2, g_Wqm2);
    cudaGetSymbolAddress((void**)&Wkm2, g_Wkm2);
    cudaGetSymbolAddress((void**)&Wvm2, g_Wvm2);
    cudaGetSymbolAddress((void**)&Wqc2, g_Wqc2);
    cudaGetSymbolAddress((void**)&Wkc2, g_Wkc2);
    cudaGetSymbolAddress((void**)&Wvc2, g_Wvc2);
    cudaGetSymbolAddress((void**)&W12, g_W12);
    cudaGetSymbolAddress((void**)&W22, g_W22);
    cudaGetSymbolAddress((void**)&Hf2, g_Hf2);

    cudaFuncSetAttribute((const void*)gemm_tc<0>,
                         cudaFuncAttributeMaxDynamicSharedMemorySize, GEMM_SMEM);
    cudaFuncSetAttribute((const void*)gemm_tc<1>,
                         cudaFuncAttributeMaxDynamicSharedMemorySize, GEMM_SMEM);
    cudaFuncSetAttribute((const void*)gemm_tc<2>,
                         cudaFuncAttributeMaxDynamicSharedMemorySize, GEMM_SMEM);
    cudaFuncSetAttribute((const void*)attn_tc<0>,
                         cudaFuncAttributeMaxDynamicSharedMemorySize, ATTN_SMEM);
    cudaFuncSetAttribute((const void*)attn_tc<1>,
                         cudaFuncAttributeMaxDynamicSharedMemorySize, ATTN_SMEM);

    // ---- single batched split launch ----
    SplitJobs J;
    const float* srcs[10]  = {wemb, pemb, Wq_m, Wk_m, Wv_m, Wq_c, Wk_c, Wv_c, W1, W2};
    __nv_bfloat16* dsts[10] = {wemb2, pemb2, Wqm2, Wkm2, Wvm2, Wqc2, Wkc2, Wvc2, W12, W22};
    int Ms[10]   = {2048, 1024, 1024, 1024, 1024, 1024, 1024, 1024, 4096, 1024};
    int Ks[10]   = {1024, 1024, 1024, 1024, 1024, 1024, 1024, 1024, 1024, 4096};
    int modes[10] = {0, 0, 1, 1, 1, 1, 1, 1, 1, 1};
    int cum = 0;
    for (int j = 0; j < 10; j++) {
        J.src[j] = srcs[j]; J.dst[j] = dsts[j];
        J.K[j] = Ks[j]; J.mode[j] = modes[j];
        J.cum[j] = cum;
        cum += Ms[j] * (Ks[j] >> 2);
    }
    J.cum[10] = cum;
    split_all<<<(cum + 255) / 256, 256>>>(J);

    // ---- launch order arranged so ncu (-s 5) captures attn_tc<1> ----
    gemm_tc<2><<<dim3(8, 16), 256, GEMM_SMEM>>>(wemb2, Wqm2, bq_m, nullptr, Q2m, 2048, 1024, 3072);  // 2
    gemm_tc<2><<<dim3(8, 16), 256, GEMM_SMEM>>>(wemb2, Wkm2, bk_m, nullptr, K2m, 2048, 1024, 3072);  // 3
    gemm_tc<2><<<dim3(8, 16), 256, GEMM_SMEM>>>(wemb2, Wvm2, bv_m, nullptr, V2m, 2048, 1024, 3072);  // 4
    gemm_tc<2><<<dim3(8, 8),  256, GEMM_SMEM>>>(pemb2, Wkc2, bk_c, nullptr, K2c, 1024, 1024, 3072);  // 5
    attn_tc<1><<<dim3(32, 16), 128, ATTN_SMEM>>>(Q2m, K2m, V2m, word2, 2048);                        // 6 <- ncu
    gemm_tc<2><<<dim3(8, 8),  256, GEMM_SMEM>>>(pemb2, Wvc2, bv_c, nullptr, V2c, 1024, 1024, 3072);  // 7
    gemm_tc<2><<<dim3(8, 16), 256, GEMM_SMEM>>>(word2, Wqc2, bq_c, nullptr, Q2c, 2048, 1024, 3072);  // 8
    attn_tc<0><<<dim3(32, 16), 128, ATTN_SMEM>>>(Q2c, K2c, V2c, cross2, 1024);                       // 9
    gemm_tc<1><<<dim3(32, 16), 256, GEMM_SMEM>>>(cross2, W12, b1, nullptr, Hf2, 2048, 4096, 3072);   // 10
    gemm_tc<0><<<dim3(8, 16),  256, GEMM_SMEM>>>(Hf2, W22, b2, out, nullptr, 2048, 1024, 12288);     // 11
}

// round 9
// speedup vs baseline: 2.6296x; 1.0520x over previous
#include <cuda_runtime.h>
#include <cuda_bf16.h>
#include <math.h>
#include <stdint.h>

// ===================== scratch (static; no allocations) =====================
__device__ __nv_bfloat16 g_Q2m[2048*2048];
__device__ __nv_bfloat16 g_K2m[2048*2048];
__device__ __nv_bfloat16 g_V2m[2048*2048];
__device__ __nv_bfloat16 g_Q2c[2048*2048];
__device__ __nv_bfloat16 g_K2c[1024*2048];
__device__ __nv_bfloat16 g_V2c[1024*2048];

__device__ __nv_bfloat16 g_wemb2 [2048*3072];
__device__ __nv_bfloat16 g_pemb2 [1024*3072];
__device__ __nv_bfloat16 g_word2 [2048*3072];
__device__ __nv_bfloat16 g_cross2[2048*3072];
__device__ __nv_bfloat16 g_Wqm2[1024*3072];
__device__ __nv_bfloat16 g_Wkm2[1024*3072];
__device__ __nv_bfloat16 g_Wvm2[1024*3072];
__device__ __nv_bfloat16 g_Wqc2[1024*3072];
__device__ __nv_bfloat16 g_Wkc2[1024*3072];
__device__ __nv_bfloat16 g_Wvc2[1024*3072];
__device__ __nv_bfloat16 g_W12 [4096*3072];
__device__ __nv_bfloat16 g_W22 [1024*12288];
__device__ __nv_bfloat16 g_Hf2 [2048*12288];

// ===================== PTX helpers =====================
__device__ __forceinline__ uint32_t smem_u32_of(const void* p) {
    uint32_t a;
    asm("{ .reg .u64 t; cvta.to.shared.u64 t, %1; cvt.u32.u64 %0, t; }" : "=r"(a) : "l"(p));
    return a;
}
#define CP_ASYNC16(sm, gp) \
    asm volatile("cp.async.cg.shared.global [%0], [%1], 16;" :: "r"(sm), "l"(gp))
#define CP_COMMIT() asm volatile("cp.async.commit_group;" ::: "memory")
#define CP_WAIT(n)  asm volatile("cp.async.wait_group %0;" :: "n"(n) : "memory")

__device__ __forceinline__ void ldm_x4(uint32_t& r0, uint32_t& r1, uint32_t& r2, uint32_t& r3,
                                       uint32_t addr) {
    asm volatile("ldmatrix.sync.aligned.m8n8.x4.shared.b16 {%0,%1,%2,%3}, [%4];"
                 : "=r"(r0), "=r"(r1), "=r"(r2), "=r"(r3) : "r"(addr));
}
__device__ __forceinline__ void ldm_x4t(uint32_t& r0, uint32_t& r1, uint32_t& r2, uint32_t& r3,
                                        uint32_t addr) {
    asm volatile("ldmatrix.sync.aligned.m8n8.x4.trans.shared.b16 {%0,%1,%2,%3}, [%4];"
                 : "=r"(r0), "=r"(r1), "=r"(r2), "=r"(r3) : "r"(addr));
}
__device__ __forceinline__ void mma16816(float* c, const uint32_t* a,
                                         uint32_t b0, uint32_t b1) {
    asm volatile("mma.sync.aligned.m16n8k16.row.col.f32.bf16.bf16.f32 "
                 "{%0,%1,%2,%3}, {%4,%5,%6,%7}, {%8,%9}, {%0,%1,%2,%3};"
                 : "+f"(c[0]), "+f"(c[1]), "+f"(c[2]), "+f"(c[3])
                 : "r"(a[0]), "r"(a[1]), "r"(a[2]), "r"(a[3]), "r"(b0), "r"(b1));
}

// ===================== split helpers =====================
__device__ __forceinline__ void split1(float v, unsigned short& h, unsigned short& l) {
    __nv_bfloat16 hb = __float2bfloat16(v);
    __nv_bfloat16 lb = __float2bfloat16(v - __bfloat162float(hb));
    h = __bfloat16_as_ushort(hb);
    l = __bfloat16_as_ushort(lb);
}
__device__ __forceinline__ void pack_hl(float a, float b, uint32_t& hi, uint32_t& lo) {
    unsigned short ha, la, hb, lb;
    split1(a, ha, la);
    split1(b, hb, lb);
    hi = ((uint32_t)hb << 16) | ha;
    lo = ((uint32_t)lb << 16) | la;
}

// ===================== batched split kernel (10 jobs, 1 launch) =============
struct SplitJobs {
    const float*  src[10];
    __nv_bfloat16* dst[10];
    int K[10];
    int mode[10];
    int cum[11];
};

__global__ __launch_bounds__(256)
void split_all(SplitJobs J)
{
    int cid = blockIdx.x * 256 + threadIdx.x;
    if (cid >= J.cum[10]) return;
    int j = 0;
    #pragma unroll
    for (int t = 0; t < 10; t++) if (cid >= J.cum[t + 1]) j = t + 1;
    int local = cid - J.cum[j];
    int K = J.K[j], kq = K >> 2;
    int m = local / kq;
    int k4 = (local - m * kq) << 2;
    float4 v = *(const float4*)(J.src[j] + (size_t)m * K + k4);
    unsigned short h0,h1,h2,h3,l0,l1,l2,l3;
    split1(v.x, h0, l0); split1(v.y, h1, l1);
    split1(v.z, h2, l2); split1(v.w, h3, l3);
    ushort4 H = make_ushort4(h0, h1, h2, h3);
    ushort4 L = make_ushort4(l0, l1, l2, l3);
    unsigned short* D = (unsigned short*)J.dst[j];
    size_t b = (size_t)m * (3 * (size_t)K);
    if (J.mode[j] == 0) {
        *(ushort4*)(D + b + k4)       = H;
        *(ushort4*)(D + b + K + k4)   = L;
        *(ushort4*)(D + b + 2*K + k4) = H;
    } else {
        *(ushort4*)(D + b + k4)       = H;
        *(ushort4*)(D + b + K + k4)   = H;
        *(ushort4*)(D + b + 2*K + k4) = L;
    }
}

// ===================== mma.sync bf16 GEMM — 512 threads, 16 warps ===========
// CTA tile 128x128, BK=32, 4-stage cp.async. Warp grid 4x4, warp tile 32x32.
// 4 warps per SMSP for latency hiding (R8 ncu: 2 warps/SMSP -> issue 24.6%).
#define NSTAGE   4
#define APITCH   80
#define STAGE_A  (128 * APITCH)
#define STAGE_AB (2 * STAGE_A)
#define GEMM_SMEM (NSTAGE * STAGE_AB)

template<int OUT_MODE>
__global__ __launch_bounds__(512, 1)
void gemm_tc(const __nv_bfloat16* __restrict__ A, const __nv_bfloat16* __restrict__ B,
             const float* __restrict__ bias, float* __restrict__ Cf,
             __nv_bfloat16* __restrict__ Cs, int M, int N, int K)
{
    extern __shared__ char smem[];
    const uint32_t sb = smem_u32_of(smem);
    const int tid = threadIdx.x, warp = tid >> 5, lane = tid & 31;
    const int warpM = (warp >> 2) * 32, warpN = (warp & 3) * 32;
    const int bm = blockIdx.y * 128, bn = blockIdx.x * 128;
    const int KT = K >> 5;

    // loader: 512 threads, 1 A chunk + 1 B chunk each (128 rows x 4 segs)
    const int lr = tid >> 2, ls = tid & 3;
    const __nv_bfloat16* Ab = A + (size_t)bm * K;
    const __nv_bfloat16* Bb = B + (size_t)bn * K;

    const int fRow = lane & 15;
    const int fK   = (lane >> 4) * 8;

    float acc[2][4][4];
    #pragma unroll
    for (int i = 0; i < 2; i++)
        #pragma unroll
        for (int j = 0; j < 4; j++)
            #pragma unroll
            for (int q = 0; q < 4; q++) acc[i][j][q] = 0.f;

    #pragma unroll
    for (int s = 0; s < NSTAGE - 1; s++) {
        uint32_t sA = sb + s * STAGE_AB, sB = sA + STAGE_A;
        int kb = s << 5;
        CP_ASYNC16(sA + lr * APITCH + ls * 16, Ab + (size_t)lr * K + kb + ls * 8);
        CP_ASYNC16(sB + lr * APITCH + ls * 16, Bb + (size_t)lr * K + kb + ls * 8);
        CP_COMMIT();
    }

    for (int t = 0; t < KT; t++) {
        CP_WAIT(NSTAGE - 2);
        __syncthreads();
        const int st = t & (NSTAGE - 1);
        const uint32_t sA = sb + st * STAGE_AB, sB = sA + STAGE_A;

        uint32_t a[2][2][4];   // [mt][kt]
        uint32_t b[2][2][4];   // [kt][np]
        #pragma unroll
        for (int mt = 0; mt < 2; mt++)
            #pragma unroll
            for (int kt = 0; kt < 2; kt++)
                ldm_x4(a[mt][kt][0], a[mt][kt][1], a[mt][kt][2], a[mt][kt][3],
                       sA + (uint32_t)(warpM + mt * 16 + fRow) * APITCH + (kt * 16 + fK) * 2);
        #pragma unroll
        for (int np = 0; np < 2; np++)
            #pragma unroll
            for (int kt = 0; kt < 2; kt++)
                ldm_x4(b[kt][np][0], b[kt][np][1], b[kt][np][2], b[kt][np][3],
                       sB + (uint32_t)(warpN + np * 16 + fRow) * APITCH + (kt * 16 + fK) * 2);

        #pragma unroll
        for (int mt = 0; mt < 2; mt++)
            #pragma unroll
            for (int np = 0; np < 2; np++)
                #pragma unroll
                for (int kt = 0; kt < 2; kt++) {
                    mma16816(acc[mt][np * 2 + 0], a[mt][kt], b[kt][np][0], b[kt][np][2]);
                    mma16816(acc[mt][np * 2 + 1], a[mt][kt], b[kt][np][1], b[kt][np][3]);
                }

        int tn = t + NSTAGE - 1;
        if (tn < KT) {
            int sn = tn & (NSTAGE - 1);
            uint32_t nA = sb + sn * STAGE_AB, nB = nA + STAGE_A;
            int kb = tn << 5;
            CP_ASYNC16(nA + lr * APITCH + ls * 16, Ab + (size_t)lr * K + kb + ls * 8);
            CP_ASYNC16(nB + lr * APITCH + ls * 16, Bb + (size_t)lr * K + kb + ls * 8);
        }
        CP_COMMIT();
    }

    #pragma unroll
    for (int mt = 0; mt < 2; mt++) {
        int rg = bm + warpM + mt * 16 + (lane >> 2);
        #pragma unroll
        for (int nt = 0; nt < 4; nt++) {
            int gcol = bn + warpN + nt * 8 + (lane & 3) * 2;
            float bx = __ldg(&bias[gcol]), by = __ldg(&bias[gcol + 1]);
            float* ac = acc[mt][nt];
            if (OUT_MODE == 0) {
                float2 v0 = make_float2(ac[0] + bx, ac[1] + by);
                float2 v1 = make_float2(ac[2] + bx, ac[3] + by);
                *(float2*)&Cf[(size_t)rg * N + gcol]       = v0;
                *(float2*)&Cf[(size_t)(rg + 8) * N + gcol] = v1;
            } else if (OUT_MODE == 1) {
                float v0 = fmaxf(ac[0] + bx, 0.f), v1 = fmaxf(ac[1] + by, 0.f);
                float v2 = fmaxf(ac[2] + bx, 0.f), v3 = fmaxf(ac[3] + by, 0.f);
                unsigned short h0,h1,h2,h3,l0,l1,l2,l3;
                split1(v0, h0, l0); split1(v1, h1, l1);
                split1(v2, h2, l2); split1(v3, h3, l3);
                unsigned short* D = (unsigned short*)Cs;
                size_t b0r = (size_t)rg * (3 * (size_t)N);
                size_t b1r = (size_t)(rg + 8) * (3 * (size_t)N);
                *(ushort2*)(D + b0r + gcol)       = make_ushort2(h0, h1);
                *(ushort2*)(D + b0r + N + gcol)   = make_ushort2(l0, l1);
                *(ushort2*)(D + b0r + 2*N + gcol) = make_ushort2(h0, h1);
                *(ushort2*)(D + b1r + gcol)       = make_ushort2(h2, h3);
                *(ushort2*)(D + b1r + N + gcol)   = make_ushort2(l2, l3);
                *(ushort2*)(D + b1r + 2*N + gcol) = make_ushort2(h2, h3);
            } else {
                float v0 = ac[0] + bx, v1 = ac[1] + by;
                float v2 = ac[2] + bx, v3 = ac[3] + by;
                unsigned short h0,h1,h2,h3,l0,l1,l2,l3;
                split1(v0, h0, l0); split1(v1, h1, l1);
                split1(v2, h2, l2); split1(v3, h3, l3);
                unsigned short* D = (unsigned short*)Cs;
                size_t b0r = (size_t)rg * (2 * (size_t)N);
                size_t b1r = (size_t)(rg + 8) * (2 * (size_t)N);
                *(ushort2*)(D + b0r + gcol)     = make_ushort2(h0, h1);
                *(ushort2*)(D + b0r + N + gcol) = make_ushort2(l0, l1);
                *(ushort2*)(D + b1r + gcol)     = make_ushort2(h2, h3);
                *(ushort2*)(D + b1r + N + gcol) = make_ushort2(l2, l3);
            }
        }
    }
}

// ===================== tensor-core flash attention (unchanged R8) ===========
#define APIT 72
#define APLANE (64 * APIT)
#define ASTAGE (4 * APLANE)
#define ATTN_SMEM (2 * ASTAGE * 2)

template<int CAUSAL>
__global__ __launch_bounds__(128)
void attn_tc(const __nv_bfloat16* __restrict__ Q2, const __nv_bfloat16* __restrict__ K2,
             const __nv_bfloat16* __restrict__ V2, __nv_bfloat16* __restrict__ O2,
             int Sk)
{
    extern __shared__ __nv_bfloat16 smb[];
    const uint32_t uS0 = smem_u32_of(smb);
    const uint32_t uS1 = uS0 + ASTAGE * 2;

    const int h = blockIdx.y;
    const int bx = CAUSAL ? ((int)gridDim.x - 1 - (int)blockIdx.x) : (int)blockIdx.x;
    const int r0 = bx * 64;
    const int tid = threadIdx.x, w = tid >> 5, lane = tid & 31;
    const int fr = lane & 15, fo = (lane >> 4) * 8;
    const uint32_t headoff = (uint32_t)h * 64;

    #pragma unroll
    for (int i = 0; i < 8; i++) {
        int cid = i * 128 + tid;
        int plane = cid >> 9, row = (cid >> 3) & 63, seg = cid & 7;
        uint32_t dst = uS1 + (uint32_t)(plane * APLANE + row * APIT + seg * 8) * 2;
        const __nv_bfloat16* src = Q2 + (size_t)(r0 + row) * 2048 + plane * 1024 + headoff + seg * 8;
        CP_ASYNC16(dst, src);
    }
    CP_COMMIT();
    #pragma unroll
    for (int i = 0; i < 16; i++) {
        int cid = i * 128 + tid;
        int plane = cid >> 9, row = (cid >> 3) & 63, seg = cid & 7;
        uint32_t dst = uS0 + (uint32_t)(plane * APLANE + row * APIT + seg * 8) * 2;
        const __nv_bfloat16* base = (plane < 2) ? K2 : V2;
        const __nv_bfloat16* src = base + (size_t)row * 2048 + (plane & 1) * 1024 + headoff + seg * 8;
        CP_ASYNC16(dst, src);
    }
    CP_COMMIT();

    CP_WAIT(1);
    __syncthreads();
    uint32_t qh[4][4], ql[4][4];
    #pragma unroll
    for (int kt = 0; kt < 4; kt++) {
        uint32_t off = (uint32_t)(w * 16 + fr) * (APIT * 2) + (kt * 16 + fo) * 2;
        ldm_x4(qh[kt][0], qh[kt][1], qh[kt][2], qh[kt][3], uS0 + ASTAGE * 2 + off);
        ldm_x4(ql[kt][0], ql[kt][1], ql[kt][2], ql[kt][3], uS0 + ASTAGE * 2 + APLANE * 2 + off);
    }
    __syncthreads();

    float o[8][4];
    #pragma unroll
    for (int n = 0; n < 8; n++)
        #pragma unroll
        for (int q = 0; q < 4; q++) o[n][q] = 0.f;
    float m0 = -1e30f, m1 = -1e30f, l0 = 0.f, l1 = 0.f;

    const int nt = CAUSAL ? (bx + 1) : (Sk >> 6);
    for (int t = 0; t < nt; t++) {
        if (t + 1 < nt) {
            const int c1 = (t + 1) * 64;
            const uint32_t uSn = ((t + 1) & 1) ? uS1 : uS0;
            #pragma unroll
            for (int i = 0; i < 16; i++) {
                int cid = i * 128 + tid;
                int plane = cid >> 9, row = (cid >> 3) & 63, seg = cid & 7;
                uint32_t dst = uSn + (uint32_t)(plane * APLANE + row * APIT + seg * 8) * 2;
                const __nv_bfloat16* base = (plane < 2) ? K2 : V2;
                const __nv_bfloat16* src = base + (size_t)(c1 + row) * 2048 + (plane & 1) * 1024 + headoff + seg * 8;
                CP_ASYNC16(dst, src);
            }
        }
        CP_COMMIT();
        CP_WAIT(1);
        __syncthreads();

        const uint32_t uKhi = ((t & 1) ? uS1 : uS0);
        const uint32_t uKlo = uKhi + APLANE * 2;
        const uint32_t uVhi = uKhi + 2 * APLANE * 2;
        const uint32_t uVlo = uKhi + 3 * APLANE * 2;
        const int c0 = t * 64;

        float s[8][4];
        #pragma unroll
        for (int n = 0; n < 8; n++)
            #pragma unroll
            for (int q = 0; q < 4; q++) s[n][q] = 0.f;
        #pragma unroll
        for (int np = 0; np < 4; np++) {
            uint32_t bh[4][4], bl[4][4];
            #pragma unroll
            for (int kt = 0; kt < 4; kt++) {
                uint32_t off = (uint32_t)(np * 16 + fr) * (APIT * 2) + (kt * 16 + fo) * 2;
                ldm_x4(bh[kt][0], bh[kt][1], bh[kt][2], bh[kt][3], uKhi + off);
                ldm_x4(bl[kt][0], bl[kt][1], bl[kt][2], bl[kt][3], uKlo + off);
            }
            #pragma unroll
            for (int kt = 0; kt < 4; kt++) {
                mma16816(s[np*2+0], qh[kt], bh[kt][0], bh[kt][2]);
                mma16816(s[np*2+1], qh[kt], bh[kt][1], bh[kt][3]);
                mma16816(s[np*2+0], ql[kt], bh[kt][0], bh[kt][2]);
                mma16816(s[np*2+1], ql[kt], bh[kt][1], bh[kt][3]);
                mma16816(s[np*2+0], qh[kt], bl[kt][0], bl[kt][2]);
                mma16816(s[np*2+1], qh[kt], bl[kt][1], bl[kt][3]);
            }
        }
        #pragma unroll
        for (int n = 0; n < 8; n++) {
            s[n][0] *= 0.125f; s[n][1] *= 0.125f;
            s[n][2] *= 0.125f; s[n][3] *= 0.125f;
        }

        if (CAUSAL && t == nt - 1) {
            int gr0 = r0 + w * 16 + (lane >> 2);
            int gr1 = gr0 + 8;
            #pragma unroll
            for (int n = 0; n < 8; n++) {
                int col = c0 + n * 8 + (lane & 3) * 2;
                if (col     > gr0) s[n][0] = -1e30f;
                if (col + 1 > gr0) s[n][1] = -1e30f;
                if (col     > gr1) s[n][2] = -1e30f;
                if (col + 1 > gr1) s[n][3] = -1e30f;
            }
        }

        float mx0 = -1e30f, mx1 = -1e30f;
        #pragma unroll
        for (int n = 0; n < 8; n++) {
            mx0 = fmaxf(mx0, fmaxf(s[n][0], s[n][1]));
            mx1 = fmaxf(mx1, fmaxf(s[n][2], s[n][3]));
        }
        mx0 = fmaxf(mx0, __shfl_xor_sync(0xffffffffu, mx0, 1));
        mx0 = fmaxf(mx0, __shfl_xor_sync(0xffffffffu, mx0, 2));
        mx1 = fmaxf(mx1, __shfl_xor_sync(0xffffffffu, mx1, 1));
        mx1 = fmaxf(mx1, __shfl_xor_sync(0xffffffffu, mx1, 2));
        float mn0 = fmaxf(m0, mx0), mn1 = fmaxf(m1, mx1);
        float cor0 = __expf(m0 - mn0), cor1 = __expf(m1 - mn1);
        m0 = mn0; m1 = mn1;
        float ps0 = 0.f, ps1 = 0.f;
        #pragma unroll
        for (int n = 0; n < 8; n++) {
            s[n][0] = __expf(s[n][0] - mn0);
            s[n][1] = __expf(s[n][1] - mn0);
            s[n][2] = __expf(s[n][2] - mn1);
            s[n][3] = __expf(s[n][3] - mn1);
            ps0 += s[n][0] + s[n][1];
            ps1 += s[n][2] + s[n][3];
        }
        ps0 += __shfl_xor_sync(0xffffffffu, ps0, 1);
        ps0 += __shfl_xor_sync(0xffffffffu, ps0, 2);
        ps1 += __shfl_xor_sync(0xffffffffu, ps1, 1);
        ps1 += __shfl_xor_sync(0xffffffffu, ps1, 2);
        l0 = l0 * cor0 + ps0;
        l1 = l1 * cor1 + ps1;
        #pragma unroll
        for (int n = 0; n < 8; n++) {
            o[n][0] *= cor0; o[n][1] *= cor0;
            o[n][2] *= cor1; o[n][3] *= cor1;
        }

        uint32_t ph[4][4], pl[4][4];
        #pragma unroll
        for (int kt = 0; kt < 4; kt++) {
            int n0 = 2 * kt, n1 = n0 + 1;
            pack_hl(s[n0][0], s[n0][1], ph[kt][0], pl[kt][0]);
            pack_hl(s[n0][2], s[n0][3], ph[kt][1], pl[kt][1]);
            pack_hl(s[n1][0], s[n1][1], ph[kt][2], pl[kt][2]);
            pack_hl(s[n1][2], s[n1][3], ph[kt][3], pl[kt][3]);
        }

        #pragma unroll
        for (int dp = 0; dp < 4; dp++) {
            uint32_t vh[4][4], vl[4][4];
            #pragma unroll
            for (int kj = 0; kj < 4; kj++) {
                uint32_t off = (uint32_t)(kj * 16 + fr) * (APIT * 2) + (dp * 16 + fo) * 2;
                ldm_x4t(vh[kj][0], vh[kj][1], vh[kj][2], vh[kj][3], uVhi + off);
                ldm_x4t(vl[kj][0], vl[kj][1], vl[kj][2], vl[kj][3], uVlo + off);
            }
            #pragma unroll
            for (int kj = 0; kj < 4; kj++) {
                mma16816(o[dp*2+0], ph[kj], vh[kj][0], vh[kj][1]);
                mma16816(o[dp*2+1], ph[kj], vh[kj][2], vh[kj][3]);
                mma16816(o[dp*2+0], pl[kj], vh[kj][0], vh[kj][1]);
                mma16816(o[dp*2+1], pl[kj], vh[kj][2], vh[kj][3]);
                mma16816(o[dp*2+0], ph[kj], vl[kj][0], vl[kj][1]);
                mma16816(o[dp*2+1], ph[kj], vl[kj][2], vl[kj][3]);
            }
        }
        __syncthreads();
    }

    float inv0 = 1.f / l0, inv1 = 1.f / l1;
    int gr0 = r0 + w * 16 + (lane >> 2);
    unsigned short* D = (unsigned short*)O2;
    #pragma unroll
    for (int n = 0; n < 8; n++) {
        int col = h * 64 + n * 8 + (lane & 3) * 2;
        float v0 = o[n][0] * inv0, v1 = o[n][1] * inv0;
        float v2 = o[n][2] * inv1, v3 = o[n][3] * inv1;
        unsigned short h0,h1,h2,h3,l0s,l1s,l2s,l3s;
        split1(v0, h0, l0s); split1(v1, h1, l1s);
        split1(v2, h2, l2s); split1(v3, h3, l3s);
        size_t b0r = (size_t)gr0 * 3072;
        size_t b1r = (size_t)(gr0 + 8) * 3072;
        *(ushort2*)(D + b0r + col)        = make_ushort2(h0, h1);
        *(ushort2*)(D + b0r + 1024 + col) = make_ushort2(l0s, l1s);
        *(ushort2*)(D + b0r + 2048 + col) = make_ushort2(h0, h1);
        *(ushort2*)(D + b1r + col)        = make_ushort2(h2, h3);
        *(ushort2*)(D + b1r + 1024 + col) = make_ushort2(l2s, l3s);
        *(ushort2*)(D + b1r + 2048 + col) = make_ushort2(h2, h3);
    }
}

// ===================== launch =====================
extern "C" void kernel_launch(void* const* d_in, const int* in_sizes, int n_in,
                              void* d_out, int out_size)
{
    const float* wemb = (const float*)d_in[0];
    const float* pemb = (const float*)d_in[1];
    const float* Wq_m = (const float*)d_in[2];
    const float* bq_m = (const float*)d_in[3];
    const float* Wk_m = (const float*)d_in[4];
    const float* bk_m = (const float*)d_in[5];
    const float* Wv_m = (const float*)d_in[6];
    const float* bv_m = (const float*)d_in[7];
    const float* Wq_c = (const float*)d_in[8];
    const float* bq_c = (const float*)d_in[9];
    const float* Wk_c = (const float*)d_in[10];
    const float* bk_c = (const float*)d_in[11];
    const float* Wv_c = (const float*)d_in[12];
    const float* bv_c = (const float*)d_in[13];
    const float* W1   = (const float*)d_in[14];
    const float* b1   = (const float*)d_in[15];
    const float* W2   = (const float*)d_in[16];
    const float* b2   = (const float*)d_in[17];
    float* out = (float*)d_out;

    __nv_bfloat16 *Q2m, *K2m, *V2m, *Q2c, *K2c, *V2c;
    __nv_bfloat16 *wemb2, *pemb2, *word2, *cross2;
    __nv_bfloat16 *Wqm2, *Wkm2, *Wvm2, *Wqc2, *Wkc2, *Wvc2, *W12, *W22, *Hf2;
    cudaGetSymbolAddress((void**)&Q2m, g_Q2m);
    cudaGetSymbolAddress((void**)&K2m, g_K2m);
    cudaGetSymbolAddress((void**)&V2m, g_V2m);
    cudaGetSymbolAddress((void**)&Q2c, g_Q2c);
    cudaGetSymbolAddress((void**)&K2c, g_K2c);
    cudaGetSymbolAddress((void**)&V2c, g_V2c);
    cudaGetSymbolAddress((void**)&wemb2, g_wemb2);
    cudaGetSymbolAddress((void**)&pemb2, g_pemb2);
    cudaGetSymbolAddress((void**)&word2, g_word2);
    cudaGetSymbolAddress((void**)&cross2, g_cross2);
    cudaGetSymbolAddress((void**)&Wqm2, g_Wqm2);
    cudaGetSymbolAddress((void**)&Wkm2, g_Wkm2);
    cudaGetSymbolAddress((void**)&Wvm2, g_Wvm2);
    cudaGetSymbolAddress((void**)&Wqc2, g_Wqc2);
    cudaGetSymbolAddress((void**)&Wkc2, g_Wkc2);
    cudaGetSymbolAddress((void**)&Wvc2, g_Wvc2);
    cudaGetSymbolAddress((void**)&W12, g_W12);
    cudaGetSymbolAddress((void**)&W22, g_W22);
    cudaGetSymbolAddress((void**)&Hf2, g_Hf2);

    cudaFuncSetAttribute((const void*)gemm_tc<0>,
                         cudaFuncAttributeMaxDynamicSharedMemorySize, GEMM_SMEM);
    cudaFuncSetAttribute((const void*)gemm_tc<1>,
                         cudaFuncAttributeMaxDynamicSharedMemorySize, GEMM_SMEM);
    cudaFuncSetAttribute((const void*)gemm_tc<2>,
                         cudaFuncAttributeMaxDynamicSharedMemorySize, GEMM_SMEM);
    cudaFuncSetAttribute((const void*)attn_tc<0>,
                         cudaFuncAttributeMaxDynamicSharedMemorySize, ATTN_SMEM);
    cudaFuncSetAttribute((const void*)attn_tc<1>,
                         cudaFuncAttributeMaxDynamicSharedMemorySize, ATTN_SMEM);

    // ---- single batched split launch ----
    SplitJobs J;
    const float* srcs[10]  = {wemb, pemb, Wq_m, Wk_m, Wv_m, Wq_c, Wk_c, Wv_c, W1, W2};
    __nv_bfloat16* dsts[10] = {wemb2, pemb2, Wqm2, Wkm2, Wvm2, Wqc2, Wkc2, Wvc2, W12, W22};
    int Ms[10]   = {2048, 1024, 1024, 1024, 1024, 1024, 1024, 1024, 4096, 1024};
    int Ks[10]   = {1024, 1024, 1024, 1024, 1024, 1024, 1024, 1024, 1024, 4096};
    int modes[10] = {0, 0, 1, 1, 1, 1, 1, 1, 1, 1};
    int cum = 0;
    for (int j = 0; j < 10; j++) {
        J.src[j] = srcs[j]; J.dst[j] = dsts[j];
        J.K[j] = Ks[j]; J.mode[j] = modes[j];
        J.cum[j] = cum;
        cum += Ms[j] * (Ks[j] >> 2);
    }
    J.cum[10] = cum;
    split_all<<<(cum + 255) / 256, 256>>>(J);

    gemm_tc<2><<<dim3(8, 16), 512, GEMM_SMEM>>>(wemb2, Wqm2, bq_m, nullptr, Q2m, 2048, 1024, 3072);
    gemm_tc<2><<<dim3(8, 16), 512, GEMM_SMEM>>>(wemb2, Wkm2, bk_m, nullptr, K2m, 2048, 1024, 3072);
    gemm_tc<2><<<dim3(8, 16), 512, GEMM_SMEM>>>(wemb2, Wvm2, bv_m, nullptr, V2m, 2048, 1024, 3072);
    gemm_tc<2><<<dim3(8, 8),  512, GEMM_SMEM>>>(pemb2, Wkc2, bk_c, nullptr, K2c, 1024, 1024, 3072);
    attn_tc<1><<<dim3(32, 16), 128, ATTN_SMEM>>>(Q2m, K2m, V2m, word2, 2048);
    gemm_tc<2><<<dim3(8, 8),  512, GEMM_SMEM>>>(pemb2, Wvc2, bv_c, nullptr, V2c, 1024, 1024, 3072);
    gemm_tc<2><<<dim3(8, 16), 512, GEMM_SMEM>>>(word2, Wqc2, bq_c, nullptr, Q2c, 2048, 1024, 3072);
    attn_tc<0><<<dim3(32, 16), 128, ATTN_SMEM>>>(Q2c, K2c, V2c, cross2, 1024);
    gemm_tc<1><<<dim3(32, 16), 512, GEMM_SMEM>>>(cross2, W12, b1, nullptr, Hf2, 2048, 4096, 3072);
    gemm_tc<0><<<dim3(8, 16),  512, GEMM_SMEM>>>(Hf2, W22, b2, out, nullptr, 2048, 1024, 12288);
}

// round 10
// speedup vs baseline: 2.6320x; 1.0009x over previous
#include <cuda_runtime.h>
#include <cuda_bf16.h>
#include <math.h>
#include <stdint.h>

// ===================== scratch (static; no allocations) =====================
// fused QKV (self): row = [Qhi|Khi|Vhi | Qlo|Klo|Vlo], stride 6144
__device__ __nv_bfloat16 g_QKV2m[2048*6144];
// fused KV (cross): row = [Khi|Vhi | Klo|Vlo], stride 4096
__device__ __nv_bfloat16 g_KV2c [1024*4096];
__device__ __nv_bfloat16 g_Q2c  [2048*2048];

__device__ __nv_bfloat16 g_wemb2 [2048*3072];
__device__ __nv_bfloat16 g_pemb2 [1024*3072];
__device__ __nv_bfloat16 g_word2 [2048*3072];
__device__ __nv_bfloat16 g_cross2[2048*3072];
__device__ __nv_bfloat16 g_Wqkvm2[3072*3072];   // concat Wq_m/Wk_m/Wv_m (B-layout)
__device__ __nv_bfloat16 g_Wqc2  [1024*3072];
__device__ __nv_bfloat16 g_Wkvc2 [2048*3072];   // concat Wk_c/Wv_c
__device__ __nv_bfloat16 g_W12   [4096*3072];
__device__ __nv_bfloat16 g_W22   [1024*12288];
__device__ __nv_bfloat16 g_Hf2   [2048*12288];

// ===================== PTX helpers =====================
__device__ __forceinline__ uint32_t smem_u32_of(const void* p) {
    uint32_t a;
    asm("{ .reg .u64 t; cvta.to.shared.u64 t, %1; cvt.u32.u64 %0, t; }" : "=r"(a) : "l"(p));
    return a;
}
#define CP_ASYNC16(sm, gp) \
    asm volatile("cp.async.cg.shared.global [%0], [%1], 16;" :: "r"(sm), "l"(gp))
#define CP_COMMIT() asm volatile("cp.async.commit_group;" ::: "memory")
#define CP_WAIT(n)  asm volatile("cp.async.wait_group %0;" :: "n"(n) : "memory")

__device__ __forceinline__ void ldm_x4(uint32_t& r0, uint32_t& r1, uint32_t& r2, uint32_t& r3,
                                       uint32_t addr) {
    asm volatile("ldmatrix.sync.aligned.m8n8.x4.shared.b16 {%0,%1,%2,%3}, [%4];"
                 : "=r"(r0), "=r"(r1), "=r"(r2), "=r"(r3) : "r"(addr));
}
__device__ __forceinline__ void ldm_x4t(uint32_t& r0, uint32_t& r1, uint32_t& r2, uint32_t& r3,
                                        uint32_t addr) {
    asm volatile("ldmatrix.sync.aligned.m8n8.x4.trans.shared.b16 {%0,%1,%2,%3}, [%4];"
                 : "=r"(r0), "=r"(r1), "=r"(r2), "=r"(r3) : "r"(addr));
}
__device__ __forceinline__ void mma16816(float* c, const uint32_t* a,
                                         uint32_t b0, uint32_t b1) {
    asm volatile("mma.sync.aligned.m16n8k16.row.col.f32.bf16.bf16.f32 "
                 "{%0,%1,%2,%3}, {%4,%5,%6,%7}, {%8,%9}, {%0,%1,%2,%3};"
                 : "+f"(c[0]), "+f"(c[1]), "+f"(c[2]), "+f"(c[3])
                 : "r"(a[0]), "r"(a[1]), "r"(a[2]), "r"(a[3]), "r"(b0), "r"(b1));
}

// ===================== split helpers =====================
__device__ __forceinline__ void split1(float v, unsigned short& h, unsigned short& l) {
    __nv_bfloat16 hb = __float2bfloat16(v);
    __nv_bfloat16 lb = __float2bfloat16(v - __bfloat162float(hb));
    h = __bfloat16_as_ushort(hb);
    l = __bfloat16_as_ushort(lb);
}
__device__ __forceinline__ void pack_hl(float a, float b, uint32_t& hi, uint32_t& lo) {
    unsigned short ha, la, hb, lb;
    split1(a, ha, la);
    split1(b, hb, lb);
    hi = ((uint32_t)hb << 16) | ha;
    lo = ((uint32_t)lb << 16) | la;
}

// ===================== batched split kernel (10 jobs, 1 launch) =============
struct SplitJobs {
    const float*  src[10];
    __nv_bfloat16* dst[10];
    int K[10];
    int mode[10];
    int cum[11];
};

__global__ __launch_bounds__(256)
void split_all(SplitJobs J)
{
    int cid = blockIdx.x * 256 + threadIdx.x;
    if (cid >= J.cum[10]) return;
    int j = 0;
    #pragma unroll
    for (int t = 0; t < 10; t++) if (cid >= J.cum[t + 1]) j = t + 1;
    int local = cid - J.cum[j];
    int K = J.K[j], kq = K >> 2;
    int m = local / kq;
    int k4 = (local - m * kq) << 2;
    float4 v = *(const float4*)(J.src[j] + (size_t)m * K + k4);
    unsigned short h0,h1,h2,h3,l0,l1,l2,l3;
    split1(v.x, h0, l0); split1(v.y, h1, l1);
    split1(v.z, h2, l2); split1(v.w, h3, l3);
    ushort4 H = make_ushort4(h0, h1, h2, h3);
    ushort4 L = make_ushort4(l0, l1, l2, l3);
    unsigned short* D = (unsigned short*)J.dst[j];
    size_t b = (size_t)m * (3 * (size_t)K);
    if (J.mode[j] == 0) {
        *(ushort4*)(D + b + k4)       = H;
        *(ushort4*)(D + b + K + k4)   = L;
        *(ushort4*)(D + b + 2*K + k4) = H;
    } else {
        *(ushort4*)(D + b + k4)       = H;
        *(ushort4*)(D + b + K + k4)   = H;
        *(ushort4*)(D + b + 2*K + k4) = L;
    }
}

// ===================== mma.sync bf16 GEMM — 128x64 tile, 256 thr, 3 CTA/SM ==
// Bias via 4x1024-segment pointer table (supports N up to 4096, incl. fused).
struct Bias4 { const float* p[4]; };

#define NSTAGE   4
#define APITCH   80
#define STAGE_A  (128 * APITCH)          // 10240
#define STAGE_B  (64 * APITCH)           // 5120
#define STAGE_AB (STAGE_A + STAGE_B)     // 15360
#define GEMM_SMEM (NSTAGE * STAGE_AB)    // 61440

template<int OUT_MODE>
__global__ __launch_bounds__(256, 3)
void gemm_tc(const __nv_bfloat16* __restrict__ A, const __nv_bfloat16* __restrict__ B,
             Bias4 bias, float* __restrict__ Cf,
             __nv_bfloat16* __restrict__ Cs, int M, int N, int K)
{
    extern __shared__ char smem[];
    const uint32_t sb = smem_u32_of(smem);
    const int tid = threadIdx.x, warp = tid >> 5, lane = tid & 31;
    const int warpM = (warp >> 1) * 32, warpN = (warp & 1) * 32;
    const int bm = blockIdx.y * 128, bn = blockIdx.x * 64;
    const int KT = K >> 5;

    // loader: A 512 chunks (2/thread), B 256 chunks (1/thread)
    const int lrA0 = tid >> 2, lrA1 = lrA0 + 64, lsg = tid & 3;
    const __nv_bfloat16* Ab = A + (size_t)bm * K;
    const __nv_bfloat16* Bb = B + (size_t)bn * K;

    const int fRow = lane & 15;
    const int fK   = (lane >> 4) * 8;

    float acc[2][4][4];
    #pragma unroll
    for (int i = 0; i < 2; i++)
        #pragma unroll
        for (int j = 0; j < 4; j++)
            #pragma unroll
            for (int q = 0; q < 4; q++) acc[i][j][q] = 0.f;

    #pragma unroll
    for (int s = 0; s < NSTAGE - 1; s++) {
        uint32_t sA = sb + s * STAGE_AB, sB = sA + STAGE_A;
        int kb = s << 5;
        CP_ASYNC16(sA + lrA0 * APITCH + lsg * 16, Ab + (size_t)lrA0 * K + kb + lsg * 8);
        CP_ASYNC16(sA + lrA1 * APITCH + lsg * 16, Ab + (size_t)lrA1 * K + kb + lsg * 8);
        CP_ASYNC16(sB + lrA0 * APITCH + lsg * 16, Bb + (size_t)lrA0 * K + kb + lsg * 8);
        CP_COMMIT();
    }

    for (int t = 0; t < KT; t++) {
        CP_WAIT(NSTAGE - 2);
        __syncthreads();
        const int st = t & (NSTAGE - 1);
        const uint32_t sA = sb + st * STAGE_AB, sB = sA + STAGE_A;

        uint32_t a[2][2][4];
        uint32_t b[2][2][4];
        #pragma unroll
        for (int mt = 0; mt < 2; mt++)
            #pragma unroll
            for (int kt = 0; kt < 2; kt++)
                ldm_x4(a[mt][kt][0], a[mt][kt][1], a[mt][kt][2], a[mt][kt][3],
                       sA + (uint32_t)(warpM + mt * 16 + fRow) * APITCH + (kt * 16 + fK) * 2);
        #pragma unroll
        for (int np = 0; np < 2; np++)
            #pragma unroll
            for (int kt = 0; kt < 2; kt++)
                ldm_x4(b[kt][np][0], b[kt][np][1], b[kt][np][2], b[kt][np][3],
                       sB + (uint32_t)(warpN + np * 16 + fRow) * APITCH + (kt * 16 + fK) * 2);

        #pragma unroll
        for (int mt = 0; mt < 2; mt++)
            #pragma unroll
            for (int np = 0; np < 2; np++)
                #pragma unroll
                for (int kt = 0; kt < 2; kt++) {
                    mma16816(acc[mt][np * 2 + 0], a[mt][kt], b[kt][np][0], b[kt][np][2]);
                    mma16816(acc[mt][np * 2 + 1], a[mt][kt], b[kt][np][1], b[kt][np][3]);
                }

        int tn = t + NSTAGE - 1;
        if (tn < KT) {
            int sn = tn & (NSTAGE - 1);
            uint32_t nA = sb + sn * STAGE_AB, nB = nA + STAGE_A;
            int kb = tn << 5;
            CP_ASYNC16(nA + lrA0 * APITCH + lsg * 16, Ab + (size_t)lrA0 * K + kb + lsg * 8);
            CP_ASYNC16(nA + lrA1 * APITCH + lsg * 16, Ab + (size_t)lrA1 * K + kb + lsg * 8);
            CP_ASYNC16(nB + lrA0 * APITCH + lsg * 16, Bb + (size_t)lrA0 * K + kb + lsg * 8);
        }
        CP_COMMIT();
    }

    #pragma unroll
    for (int mt = 0; mt < 2; mt++) {
        int rg = bm + warpM + mt * 16 + (lane >> 2);
        #pragma unroll
        for (int nt = 0; nt < 4; nt++) {
            int gcol = bn + warpN + nt * 8 + (lane & 3) * 2;
            float bx = __ldg(&bias.p[gcol >> 10][gcol & 1023]);
            float by = __ldg(&bias.p[(gcol + 1) >> 10][(gcol + 1) & 1023]);
            float* ac = acc[mt][nt];
            if (OUT_MODE == 0) {
                float2 v0 = make_float2(ac[0] + bx, ac[1] + by);
                float2 v1 = make_float2(ac[2] + bx, ac[3] + by);
                *(float2*)&Cf[(size_t)rg * N + gcol]       = v0;
                *(float2*)&Cf[(size_t)(rg + 8) * N + gcol] = v1;
            } else if (OUT_MODE == 1) {
                float v0 = fmaxf(ac[0] + bx, 0.f), v1 = fmaxf(ac[1] + by, 0.f);
                float v2 = fmaxf(ac[2] + bx, 0.f), v3 = fmaxf(ac[3] + by, 0.f);
                unsigned short h0,h1,h2,h3,l0,l1,l2,l3;
                split1(v0, h0, l0); split1(v1, h1, l1);
                split1(v2, h2, l2); split1(v3, h3, l3);
                unsigned short* D = (unsigned short*)Cs;
                size_t b0r = (size_t)rg * (3 * (size_t)N);
                size_t b1r = (size_t)(rg + 8) * (3 * (size_t)N);
                *(ushort2*)(D + b0r + gcol)       = make_ushort2(h0, h1);
                *(ushort2*)(D + b0r + N + gcol)   = make_ushort2(l0, l1);
                *(ushort2*)(D + b0r + 2*N + gcol) = make_ushort2(h0, h1);
                *(ushort2*)(D + b1r + gcol)       = make_ushort2(h2, h3);
                *(ushort2*)(D + b1r + N + gcol)   = make_ushort2(l2, l3);
                *(ushort2*)(D + b1r + 2*N + gcol) = make_ushort2(h2, h3);
            } else {
                float v0 = ac[0] + bx, v1 = ac[1] + by;
                float v2 = ac[2] + bx, v3 = ac[3] + by;
                unsigned short h0,h1,h2,h3,l0,l1,l2,l3;
                split1(v0, h0, l0); split1(v1, h1, l1);
                split1(v2, h2, l2); split1(v3, h3, l3);
                unsigned short* D = (unsigned short*)Cs;
                size_t b0r = (size_t)rg * (2 * (size_t)N);
                size_t b1r = (size_t)(rg + 8) * (2 * (size_t)N);
                *(ushort2*)(D + b0r + gcol)     = make_ushort2(h0, h1);
                *(ushort2*)(D + b0r + N + gcol) = make_ushort2(l0, l1);
                *(ushort2*)(D + b1r + gcol)     = make_ushort2(h2, h3);
                *(ushort2*)(D + b1r + N + gcol) = make_ushort2(l2, l3);
            }
        }
    }
}

// ===================== tensor-core flash attention (strided inputs) =========
#define APIT 72
#define APLANE (64 * APIT)
#define ASTAGE (4 * APLANE)
#define ATTN_SMEM (2 * ASTAGE * 2)

template<int CAUSAL>
__global__ __launch_bounds__(128)
void attn_tc(const __nv_bfloat16* __restrict__ Qb, const __nv_bfloat16* __restrict__ Kb,
             const __nv_bfloat16* __restrict__ Vb, __nv_bfloat16* __restrict__ O2,
             int Sk, int qstride, int qlooff, int kvstride, int kvlooff)
{
    extern __shared__ __nv_bfloat16 smb[];
    const uint32_t uS0 = smem_u32_of(smb);
    const uint32_t uS1 = uS0 + ASTAGE * 2;

    const int h = blockIdx.y;
    const int bx = CAUSAL ? ((int)gridDim.x - 1 - (int)blockIdx.x) : (int)blockIdx.x;
    const int r0 = bx * 64;
    const int tid = threadIdx.x, w = tid >> 5, lane = tid & 31;
    const int fr = lane & 15, fo = (lane >> 4) * 8;
    const int headoff = h * 64;

    #pragma unroll
    for (int i = 0; i < 8; i++) {
        int cid = i * 128 + tid;
        int plane = cid >> 9, row = (cid >> 3) & 63, seg = cid & 7;
        uint32_t dst = uS1 + (uint32_t)(plane * APLANE + row * APIT + seg * 8) * 2;
        const __nv_bfloat16* src = Qb + (size_t)(r0 + row) * qstride + plane * qlooff + headoff + seg * 8;
        CP_ASYNC16(dst, src);
    }
    CP_COMMIT();
    #pragma unroll
    for (int i = 0; i < 16; i++) {
        int cid = i * 128 + tid;
        int plane = cid >> 9, row = (cid >> 3) & 63, seg = cid & 7;
        uint32_t dst = uS0 + (uint32_t)(plane * APLANE + row * APIT + seg * 8) * 2;
        const __nv_bfloat16* base = (plane < 2) ? Kb : Vb;
        const __nv_bfloat16* src = base + (size_t)row * kvstride + (plane & 1) * kvlooff + headoff + seg * 8;
        CP_ASYNC16(dst, src);
    }
    CP_COMMIT();

    CP_WAIT(1);
    __syncthreads();
    uint32_t qh[4][4], ql[4][4];
    #pragma unroll
    for (int kt = 0; kt < 4; kt++) {
        uint32_t off = (uint32_t)(w * 16 + fr) * (APIT * 2) + (kt * 16 + fo) * 2;
        ldm_x4(qh[kt][0], qh[kt][1], qh[kt][2], qh[kt][3], uS0 + ASTAGE * 2 + off);
        ldm_x4(ql[kt][0], ql[kt][1], ql[kt][2], ql[kt][3], uS0 + ASTAGE * 2 + APLANE * 2 + off);
    }
    __syncthreads();

    float o[8][4];
    #pragma unroll
    for (int n = 0; n < 8; n++)
        #pragma unroll
        for (int q = 0; q < 4; q++) o[n][q] = 0.f;
    float m0 = -1e30f, m1 = -1e30f, l0 = 0.f, l1 = 0.f;

    const int nt = CAUSAL ? (bx + 1) : (Sk >> 6);
    for (int t = 0; t < nt; t++) {
        if (t + 1 < nt) {
            const int c1 = (t + 1) * 64;
            const uint32_t uSn = ((t + 1) & 1) ? uS1 : uS0;
            #pragma unroll
            for (int i = 0; i < 16; i++) {
                int cid = i * 128 + tid;
                int plane = cid >> 9, row = (cid >> 3) & 63, seg = cid & 7;
                uint32_t dst = uSn + (uint32_t)(plane * APLANE + row * APIT + seg * 8) * 2;
                const __nv_bfloat16* base = (plane < 2) ? Kb : Vb;
                const __nv_bfloat16* src = base + (size_t)(c1 + row) * kvstride + (plane & 1) * kvlooff + headoff + seg * 8;
                CP_ASYNC16(dst, src);
            }
        }
        CP_COMMIT();
        CP_WAIT(1);
        __syncthreads();

        const uint32_t uKhi = ((t & 1) ? uS1 : uS0);
        const uint32_t uKlo = uKhi + APLANE * 2;
        const uint32_t uVhi = uKhi + 2 * APLANE * 2;
        const uint32_t uVlo = uKhi + 3 * APLANE * 2;
        const int c0 = t * 64;

        float s[8][4];
        #pragma unroll
        for (int n = 0; n < 8; n++)
            #pragma unroll
            for (int q = 0; q < 4; q++) s[n][q] = 0.f;
        #pragma unroll
        for (int np = 0; np < 4; np++) {
            uint32_t bh[4][4], bl[4][4];
            #pragma unroll
            for (int kt = 0; kt < 4; kt++) {
                uint32_t off = (uint32_t)(np * 16 + fr) * (APIT * 2) + (kt * 16 + fo) * 2;
                ldm_x4(bh[kt][0], bh[kt][1], bh[kt][2], bh[kt][3], uKhi + off);
                ldm_x4(bl[kt][0], bl[kt][1], bl[kt][2], bl[kt][3], uKlo + off);
            }
            #pragma unroll
            for (int kt = 0; kt < 4; kt++) {
                mma16816(s[np*2+0], qh[kt], bh[kt][0], bh[kt][2]);
                mma16816(s[np*2+1], qh[kt], bh[kt][1], bh[kt][3]);
                mma16816(s[np*2+0], ql[kt], bh[kt][0], bh[kt][2]);
                mma16816(s[np*2+1], ql[kt], bh[kt][1], bh[kt][3]);
                mma16816(s[np*2+0], qh[kt], bl[kt][0], bl[kt][2]);
                mma16816(s[np*2+1], qh[kt], bl[kt][1], bl[kt][3]);
            }
        }
        #pragma unroll
        for (int n = 0; n < 8; n++) {
            s[n][0] *= 0.125f; s[n][1] *= 0.125f;
            s[n][2] *= 0.125f; s[n][3] *= 0.125f;
        }

        if (CAUSAL && t == nt - 1) {
            int gr0 = r0 + w * 16 + (lane >> 2);
            int gr1 = gr0 + 8;
            #pragma unroll
            for (int n = 0; n < 8; n++) {
                int col = c0 + n * 8 + (lane & 3) * 2;
                if (col     > gr0) s[n][0] = -1e30f;
                if (col + 1 > gr0) s[n][1] = -1e30f;
                if (col     > gr1) s[n][2] = -1e30f;
                if (col + 1 > gr1) s[n][3] = -1e30f;
            }
        }

        float mx0 = -1e30f, mx1 = -1e30f;
        #pragma unroll
        for (int n = 0; n < 8; n++) {
            mx0 = fmaxf(mx0, fmaxf(s[n][0], s[n][1]));
            mx1 = fmaxf(mx1, fmaxf(s[n][2], s[n][3]));
        }
        mx0 = fmaxf(mx0, __shfl_xor_sync(0xffffffffu, mx0, 1));
        mx0 = fmaxf(mx0, __shfl_xor_sync(0xffffffffu, mx0, 2));
        mx1 = fmaxf(mx1, __shfl_xor_sync(0xffffffffu, mx1, 1));
        mx1 = fmaxf(mx1, __shfl_xor_sync(0xffffffffu, mx1, 2));
        float mn0 = fmaxf(m0, mx0), mn1 = fmaxf(m1, mx1);
        float cor0 = __expf(m0 - mn0), cor1 = __expf(m1 - mn1);
        m0 = mn0; m1 = mn1;
        float ps0 = 0.f, ps1 = 0.f;
        #pragma unroll
        for (int n = 0; n < 8; n++) {
            s[n][0] = __expf(s[n][0] - mn0);
            s[n][1] = __expf(s[n][1] - mn0);
            s[n][2] = __expf(s[n][2] - mn1);
            s[n][3] = __expf(s[n][3] - mn1);
            ps0 += s[n][0] + s[n][1];
            ps1 += s[n][2] + s[n][3];
        }
        ps0 += __shfl_xor_sync(0xffffffffu, ps0, 1);
        ps0 += __shfl_xor_sync(0xffffffffu, ps0, 2);
        ps1 += __shfl_xor_sync(0xffffffffu, ps1, 1);
        ps1 += __shfl_xor_sync(0xffffffffu, ps1, 2);
        l0 = l0 * cor0 + ps0;
        l1 = l1 * cor1 + ps1;
        #pragma unroll
        for (int n = 0; n < 8; n++) {
            o[n][0] *= cor0; o[n][1] *= cor0;
            o[n][2] *= cor1; o[n][3] *= cor1;
        }

        uint32_t ph[4][4], pl[4][4];
        #pragma unroll
        for (int kt = 0; kt < 4; kt++) {
            int n0 = 2 * kt, n1 = n0 + 1;
            pack_hl(s[n0][0], s[n0][1], ph[kt][0], pl[kt][0]);
            pack_hl(s[n0][2], s[n0][3], ph[kt][1], pl[kt][1]);
            pack_hl(s[n1][0], s[n1][1], ph[kt][2], pl[kt][2]);
            pack_hl(s[n1][2], s[n1][3], ph[kt][3], pl[kt][3]);
        }

        #pragma unroll
        for (int dp = 0; dp < 4; dp++) {
            uint32_t vh[4][4], vl[4][4];
            #pragma unroll
            for (int kj = 0; kj < 4; kj++) {
                uint32_t off = (uint32_t)(kj * 16 + fr) * (APIT * 2) + (dp * 16 + fo) * 2;
                ldm_x4t(vh[kj][0], vh[kj][1], vh[kj][2], vh[kj][3], uVhi + off);
                ldm_x4t(vl[kj][0], vl[kj][1], vl[kj][2], vl[kj][3], uVlo + off);
            }
            #pragma unroll
            for (int kj = 0; kj < 4; kj++) {
                mma16816(o[dp*2+0], ph[kj], vh[kj][0], vh[kj][1]);
                mma16816(o[dp*2+1], ph[kj], vh[kj][2], vh[kj][3]);
                mma16816(o[dp*2+0], pl[kj], vh[kj][0], vh[kj][1]);
                mma16816(o[dp*2+1], pl[kj], vh[kj][2], vh[kj][3]);
                mma16816(o[dp*2+0], ph[kj], vl[kj][0], vl[kj][1]);
                mma16816(o[dp*2+1], ph[kj], vl[kj][2], vl[kj][3]);
            }
        }
        __syncthreads();
    }

    float inv0 = 1.f / l0, inv1 = 1.f / l1;
    int gr0 = r0 + w * 16 + (lane >> 2);
    unsigned short* D = (unsigned short*)O2;
    #pragma unroll
    for (int n = 0; n < 8; n++) {
        int col = h * 64 + n * 8 + (lane & 3) * 2;
        float v0 = o[n][0] * inv0, v1 = o[n][1] * inv0;
        float v2 = o[n][2] * inv1, v3 = o[n][3] * inv1;
        unsigned short h0,h1,h2,h3,l0s,l1s,l2s,l3s;
        split1(v0, h0, l0s); split1(v1, h1, l1s);
        split1(v2, h2, l2s); split1(v3, h3, l3s);
        size_t b0r = (size_t)gr0 * 3072;
        size_t b1r = (size_t)(gr0 + 8) * 3072;
        *(ushort2*)(D + b0r + col)        = make_ushort2(h0, h1);
        *(ushort2*)(D + b0r + 1024 + col) = make_ushort2(l0s, l1s);
        *(ushort2*)(D + b0r + 2048 + col) = make_ushort2(h0, h1);
        *(ushort2*)(D + b1r + col)        = make_ushort2(h2, h3);
        *(ushort2*)(D + b1r + 1024 + col) = make_ushort2(l2s, l3s);
        *(ushort2*)(D + b1r + 2048 + col) = make_ushort2(h2, h3);
    }
}

// ===================== launch =====================
extern "C" void kernel_launch(void* const* d_in, const int* in_sizes, int n_in,
                              void* d_out, int out_size)
{
    const float* wemb = (const float*)d_in[0];
    const float* pemb = (const float*)d_in[1];
    const float* Wq_m = (const float*)d_in[2];
    const float* bq_m = (const float*)d_in[3];
    const float* Wk_m = (const float*)d_in[4];
    const float* bk_m = (const float*)d_in[5];
    const float* Wv_m = (const float*)d_in[6];
    const float* bv_m = (const float*)d_in[7];
    const float* Wq_c = (const float*)d_in[8];
    const float* bq_c = (const float*)d_in[9];
    const float* Wk_c = (const float*)d_in[10];
    const float* bk_c = (const float*)d_in[11];
    const float* Wv_c = (const float*)d_in[12];
    const float* bv_c = (const float*)d_in[13];
    const float* W1   = (const float*)d_in[14];
    const float* b1   = (const float*)d_in[15];
    const float* W2   = (const float*)d_in[16];
    const float* b2   = (const float*)d_in[17];
    float* out = (float*)d_out;

    __nv_bfloat16 *QKV2m, *KV2c, *Q2c;
    __nv_bfloat16 *wemb2, *pemb2, *word2, *cross2;
    __nv_bfloat16 *Wqkvm2, *Wqc2, *Wkvc2, *W12, *W22, *Hf2;
    cudaGetSymbolAddress((void**)&QKV2m, g_QKV2m);
    cudaGetSymbolAddress((void**)&KV2c, g_KV2c);
    cudaGetSymbolAddress((void**)&Q2c, g_Q2c);
    cudaGetSymbolAddress((void**)&wemb2, g_wemb2);
    cudaGetSymbolAddress((void**)&pemb2, g_pemb2);
    cudaGetSymbolAddress((void**)&word2, g_word2);
    cudaGetSymbolAddress((void**)&cross2, g_cross2);
    cudaGetSymbolAddress((void**)&Wqkvm2, g_Wqkvm2);
    cudaGetSymbolAddress((void**)&Wqc2, g_Wqc2);
    cudaGetSymbolAddress((void**)&Wkvc2, g_Wkvc2);
    cudaGetSymbolAddress((void**)&W12, g_W12);
    cudaGetSymbolAddress((void**)&W22, g_W22);
    cudaGetSymbolAddress((void**)&Hf2, g_Hf2);

    cudaFuncSetAttribute((const void*)gemm_tc<0>,
                         cudaFuncAttributeMaxDynamicSharedMemorySize, GEMM_SMEM);
    cudaFuncSetAttribute((const void*)gemm_tc<1>,
                         cudaFuncAttributeMaxDynamicSharedMemorySize, GEMM_SMEM);
    cudaFuncSetAttribute((const void*)gemm_tc<2>,
                         cudaFuncAttributeMaxDynamicSharedMemorySize, GEMM_SMEM);
    cudaFuncSetAttribute((const void*)attn_tc<0>,
                         cudaFuncAttributeMaxDynamicSharedMemorySize, ATTN_SMEM);
    cudaFuncSetAttribute((const void*)attn_tc<1>,
                         cudaFuncAttributeMaxDynamicSharedMemorySize, ATTN_SMEM);

    // ---- single batched split launch (weights concatenated for fused GEMMs)
    SplitJobs J;
    const float* srcs[10]  = {wemb, pemb, Wq_m, Wk_m, Wv_m, Wq_c, Wk_c, Wv_c, W1, W2};
    __nv_bfloat16* dsts[10] = {wemb2, pemb2,
                               Wqkvm2, Wqkvm2 + (size_t)1024*3072, Wqkvm2 + (size_t)2048*3072,
                               Wqc2,
                               Wkvc2, Wkvc2 + (size_t)1024*3072,
                               W12, W22};
    int Ms[10]   = {2048, 1024, 1024, 1024, 1024, 1024, 1024, 1024, 4096, 1024};
    int Ks[10]   = {1024, 1024, 1024, 1024, 1024, 1024, 1024, 1024, 1024, 4096};
    int modes[10] = {0, 0, 1, 1, 1, 1, 1, 1, 1, 1};
    int cum = 0;
    for (int j = 0; j < 10; j++) {
        J.src[j] = srcs[j]; J.dst[j] = dsts[j];
        J.K[j] = Ks[j]; J.mode[j] = modes[j];
        J.cum[j] = cum;
        cum += Ms[j] * (Ks[j] >> 2);
    }
    J.cum[10] = cum;
    split_all<<<(cum + 255) / 256, 256>>>(J);                                           // 1

    Bias4 Bqkv  = {{bq_m, bk_m, bv_m, bq_m}};
    Bias4 Bkvc  = {{bk_c, bv_c, bk_c, bv_c}};
    Bias4 Bqc   = {{bq_c, bq_c, bq_c, bq_c}};
    Bias4 Bf1   = {{b1, b1 + 1024, b1 + 2048, b1 + 3072}};
    Bias4 Bf2   = {{b2, b2, b2, b2}};

    // fused QKV(self): N=3072, out stride 6144
    gemm_tc<2><<<dim3(48, 16), 256, GEMM_SMEM>>>(wemb2, Wqkvm2, Bqkv, nullptr, QKV2m, 2048, 3072, 3072); // 2
    // fused KV(cross): N=2048, out stride 4096
    gemm_tc<2><<<dim3(32, 8),  256, GEMM_SMEM>>>(pemb2, Wkvc2, Bkvc, nullptr, KV2c, 1024, 2048, 3072);   // 3
    // causal self-attention
    attn_tc<1><<<dim3(32, 16), 128, ATTN_SMEM>>>(QKV2m, QKV2m + 1024, QKV2m + 2048, word2,
                                                 2048, 6144, 3072, 6144, 3072);                          // 4
    // cross Q projection
    gemm_tc<2><<<dim3(16, 16), 256, GEMM_SMEM>>>(word2, Wqc2, Bqc, nullptr, Q2c, 2048, 1024, 3072);      // 5
    // cross attention  <- ncu -s 5 captures this
    attn_tc<0><<<dim3(32, 16), 128, ATTN_SMEM>>>(Q2c, KV2c, KV2c + 1024, cross2,
                                                 1024, 2048, 1024, 4096, 2048);                          // 6
    // FFN
    gemm_tc<1><<<dim3(64, 16), 256, GEMM_SMEM>>>(cross2, W12, Bf1, nullptr, Hf2, 2048, 4096, 3072);      // 7
    gemm_tc<0><<<dim3(16, 16), 256, GEMM_SMEM>>>(Hf2, W22, Bf2, out, nullptr, 2048, 1024, 12288);        // 8
}